// round 10
// baseline (speedup 1.0000x reference)
#include <cuda_runtime.h>
#include <math.h>

#define B_    64
#define T_    512
#define EMB_  256
#define HD_   256
#define G4_   1024
#define TAGS_ 11
#define NEGV  (-10000.0f)
#define GSTRIDE (256 * 64)   // gate stride in g_Gx elements

// ---------------- scratch (static device globals; no allocs) ----------------
__device__ __align__(16) float g_Gx[(long)2 * T_ * B_ * G4_];   // [dir][t][gate][unit][b]
__device__ __align__(16) float g_Hout[(long)2 * T_ * B_ * HD_]; // [dir][t][unit][b]
__device__ __align__(16) float g_hbuf[2 * 2 * B_ * HD_];        // [dir][buf][unitq][b] float4
__device__ __align__(16) float g_feats[T_ * B_ * TAGS_];
#define LSTM_NB 128
__device__ unsigned g_flags[LSTM_NB];   // monotonic epochs across graph replays

// ---------------- packed f32x2 helpers ----------------
__device__ __forceinline__ void ffma2(unsigned long long& d,
                                      unsigned long long a,
                                      unsigned long long b) {
    asm("fma.rn.f32x2 %0, %1, %2, %0;" : "+l"(d) : "l"(a), "l"(b));
}
__device__ __forceinline__ float2 upk(unsigned long long v) {
    float2 f; asm("mov.b64 {%0, %1}, %2;" : "=f"(f.x), "=f"(f.y) : "l"(v)); return f;
}

// ---------------- fast activations (MUFU-based, ~1e-6 rel err) ----------------
__device__ __forceinline__ float sigf(float x) {
    return __fdividef(1.f, 1.f + __expf(-x));
}
__device__ __forceinline__ float tanhfast(float x) {
    return fmaf(2.f, __fdividef(1.f, 1.f + __expf(-2.f * x)), -1.f);
}

// ---------------- release/acquire flag ops ----------------
__device__ __forceinline__ unsigned ld_acq(const unsigned* p) {
    unsigned v;
    asm volatile("ld.global.acquire.gpu.u32 %0, [%1];" : "=r"(v) : "l"(p));
    return v;
}
__device__ __forceinline__ void st_rel(unsigned* p, unsigned v) {
    asm volatile("st.global.release.gpu.u32 [%0], %1;" :: "l"(p), "r"(v) : "memory");
}

// ---------------- cp.async helpers ----------------
__device__ __forceinline__ void cp16(unsigned daddr, const void* src) {
    asm volatile("cp.async.cg.shared.global [%0], [%1], 16;"
                 :: "r"(daddr), "l"(src) : "memory");
}
#define CP_COMMIT() asm volatile("cp.async.commit_group;" ::: "memory")
#define CP_WAIT(N)  asm volatile("cp.async.wait_group %0;" :: "n"(N) : "memory")

// =====================================================================
// K1: Gx = embed[sent] @ Wih.T + b, written as [dir][t][gate][unit][b].
// Epilogue staged through smem tile [128 cols][64 b] (stride 68),
// then fully-coalesced float4 stores.
// =====================================================================
#define GX_STAGE_FLOATS (128 * 68)

__global__ void gx_kernel(const int* __restrict__ sent,
                          const float* __restrict__ embed,
                          const float* __restrict__ Wf, const float* __restrict__ bf,
                          const float* __restrict__ Wb, const float* __restrict__ bb)
{
    __shared__ __align__(16) float Sm[GX_STAGE_FLOATS];
    float* As = Sm;                // [row][k] stride 36
    float* Bs = Sm + 64 * 36;      // [col][k] stride 36
    __shared__ int toks[64];

    const int t     = blockIdx.x;
    const int dir   = blockIdx.y >> 3;
    const int gcol0 = (blockIdx.y & 7) * 128;
    const float* __restrict__ W    = dir ? Wb : Wf;
    const float* __restrict__ bias = dir ? bb : bf;

    const int tid = threadIdx.x;
    if (tid < 64) toks[tid] = sent[tid * T_ + t];
    __syncthreads();

    const int rowg = tid & 7;
    const int colg = tid >> 3;

    unsigned long long acc[8][4];
#pragma unroll
    for (int i = 0; i < 8; i++)
#pragma unroll
        for (int j = 0; j < 4; j++) acc[i][j] = 0ull;

    for (int k0 = 0; k0 < EMB_; k0 += 32) {
#pragma unroll
        for (int i = 0; i < 2; i++) {
            int e = tid + i * 256, r = e >> 3, seg = e & 7;
            float4 va = *(const float4*)(embed + (long)toks[r] * EMB_ + k0 + seg * 4);
            *(float4*)&As[r * 36 + seg * 4] = va;
        }
#pragma unroll
        for (int i = 0; i < 4; i++) {
            int e = tid + i * 256, r = e >> 3, seg = e & 7;
            float4 vb = *(const float4*)(W + (long)(gcol0 + r) * EMB_ + k0 + seg * 4);
            *(float4*)&Bs[r * 36 + seg * 4] = vb;
        }
        __syncthreads();
#pragma unroll
        for (int k4 = 0; k4 < 8; k4++) {
            ulonglong2 bv[4];
#pragma unroll
            for (int j = 0; j < 4; j++)
                bv[j] = *(const ulonglong2*)&Bs[(colg * 4 + j) * 36 + k4 * 4];
#pragma unroll
            for (int i = 0; i < 8; i++) {
                ulonglong2 av = *(const ulonglong2*)&As[(rowg + 8 * i) * 36 + k4 * 4];
#pragma unroll
                for (int j = 0; j < 4; j++) {
                    ffma2(acc[i][j], av.x, bv[j].x);
                    ffma2(acc[i][j], av.y, bv[j].y);
                }
            }
        }
        __syncthreads();
    }
    __syncthreads();

    float* stage = Sm;
#pragma unroll
    for (int j = 0; j < 4; j++) {
        int colL = colg * 4 + j;
        float bsv = bias[gcol0 + colL];
#pragma unroll
        for (int i = 0; i < 8; i++) {
            float2 p = upk(acc[i][j]);
            stage[colL * 68 + rowg + 8 * i] = p.x + p.y + bsv;
        }
    }
    __syncthreads();

    const long tb = (long)dir * T_ + t;
#pragma unroll
    for (int i = 0; i < 8; i++) {
        int id   = tid + i * 256;
        int colL = id >> 4;
        int b4   = id & 15;
        int gcol = gcol0 + colL;
        long obase = ((tb * 4 + (gcol >> 8)) * 256 + (gcol & 255)) * 64;
        float4 v = *(float4*)&stage[colL * 68 + b4 * 4];
        *(float4*)(g_Gx + obase + b4 * 4) = v;
    }
}

// =====================================================================
// K2: persistent bidirectional LSTM, 128 CTAs x 256 threads.
// CTA = (dir, kq 4-unit group); thread b=tid&63, u=tid>>6.
// Quarter-split flags + cp.async pipelined h staging (overlap L2 with FMA).
// CORRECT h indexing: hs2[kk*64+b] = h[4kk..4kk+3, b].
// =====================================================================
#define WSTRIDE   260
#define SM_WSH    0
#define SM_HS4    (16 * WSTRIDE)
#define SM_SHH    (SM_HS4 + 64 * 64 * 4)
#define LSTM_SMEM ((SM_SHH + 256) * 4)

__global__ void __launch_bounds__(256, 1)
lstm_kernel(const float* __restrict__ Whh_f, const float* __restrict__ Whh_b,
            const float* __restrict__ h0f, const float* __restrict__ c0f,
            const float* __restrict__ h0b, const float* __restrict__ c0b,
            const float* __restrict__ mask)
{
    extern __shared__ __align__(16) float sm[];
    float*  Wsh  = sm + SM_WSH;
    float4* hs4  = (float4*)(sm + SM_HS4);
    float*  sh_h = sm + SM_SHH;

    const int cta = blockIdx.x;
    const int dir = cta >> 6;
    const int kq  = cta & 63;
    const int u0  = kq * 4;
    const int tid = threadIdx.x;
    const int b    = tid & 63;
    const int u    = tid >> 6;
    const int unit = u0 + u;

    const float* __restrict__ Whh = dir ? Whh_b : Whh_f;
    const float* __restrict__ h0  = dir ? h0b : h0f;
    const float* __restrict__ c0  = dir ? c0b : c0f;

    float4* hbuf0 = ((float4*)g_hbuf) + (dir * 2 + 0) * (64 * 64);
    float4* hbuf1 = ((float4*)g_hbuf) + (dir * 2 + 1) * (64 * 64);
    float4* HoutD = ((float4*)g_Hout) + (long)dir * T_ * 64 * 64;
    unsigned* myflag = &g_flags[cta];
    const unsigned* dflags = &g_flags[dir * 64];

    const unsigned hsaddr = (unsigned)__cvta_generic_to_shared(hs4);

    __shared__ unsigned sbase;
    if (tid == 0) sbase = ld_acq(myflag);
    __syncthreads();
    const unsigned base = sbase;

    // preload weight slice: Wsh[g*4+uu][k] = Whh[g*256 + u0+uu][k]
#pragma unroll
    for (int i = 0; i < 4; i++) {
        int f  = tid + i * 256;
        int r  = f >> 6;
        int k4 = f & 63;
        int grow = (r >> 2) * HD_ + u0 + (r & 3);
        float4 w = *(const float4*)(Whh + (long)grow * HD_ + k4 * 4);
        *(float4*)&Wsh[r * WSTRIDE + k4 * 4] = w;
    }

    float c = c0[b * HD_ + unit];
    float h = h0[b * HD_ + unit];

    sh_h[u * 64 + b] = h;
    __syncthreads();
    if (tid < 64) {
        float4 v = make_float4(sh_h[tid], sh_h[64 + tid], sh_h[128 + tid], sh_h[192 + tid]);
        __stcg(&hbuf0[kq * 64 + tid], v);
    }
    __syncthreads();
    if (tid == 0) st_rel(myflag, base + 1);

    const float* w0p = &Wsh[(0 + u) * WSTRIDE];
    const float* w1p = &Wsh[(4 + u) * WSTRIDE];
    const float* w2p = &Wsh[(8 + u) * WSTRIDE];
    const float* w3p = &Wsh[(12 + u) * WSTRIDE];
    const ulonglong2* hs2 = (const ulonglong2*)hs4;

#define DOT_RANGE(K0, K1)                                              \
    _Pragma("unroll 8")                                                \
    for (int kk = (K0); kk < (K1); kk++) {                             \
        ulonglong2 hv = hs2[kk * 64 + b];                              \
        ulonglong2 w0 = *(const ulonglong2*)&w0p[kk * 4];              \
        ulonglong2 w1 = *(const ulonglong2*)&w1p[kk * 4];              \
        ulonglong2 w2 = *(const ulonglong2*)&w2p[kk * 4];              \
        ulonglong2 w3 = *(const ulonglong2*)&w3p[kk * 4];              \
        ffma2(a0p, hv.x, w0.x); ffma2(a0p, hv.y, w0.y);                \
        ffma2(a1p, hv.x, w1.x); ffma2(a1p, hv.y, w1.y);                \
        ffma2(a2p, hv.x, w2.x); ffma2(a2p, hv.y, w2.y);                \
        ffma2(a3p, hv.x, w3.x); ffma2(a3p, hv.y, w3.y);                \
    }

    for (int s = 0; s < T_; s++) {
        const int t = dir ? (T_ - 1 - s) : s;
        const int p = s & 1;

        // prefetch gate pre-activations + mask (independent of barrier)
        const float* gx = g_Gx + (((long)dir * T_ + t) * 4 * 256 + unit) * 64 + b;
        float ga0 = __ldg(gx);
        float ga1 = __ldg(gx + GSTRIDE);
        float ga2 = __ldg(gx + 2 * GSTRIDE);
        float ga3 = __ldg(gx + 3 * GSTRIDE);
        float mt  = __ldg(mask + t * B_ + b);

        const float4* hin = p ? hbuf1 : hbuf0;

        // ---- issue phase: per quarter, poll 16 flags then cp.async 16KB ----
#pragma unroll
        for (int q = 0; q < 4; q++) {
            if (tid < 16) {
                const unsigned* f = dflags + q * 16 + tid;
                while ((int)(ld_acq(f) - base) < (int)(s + 1)) { }
            }
            __syncthreads();
#pragma unroll
            for (int i = 0; i < 4; i++) {
                int e = q * 1024 + tid + i * 256;
                cp16(hsaddr + e * 16, hin + e);
            }
            CP_COMMIT();
        }

        // ---- compute phase: consume quarters as they land ----
        unsigned long long a0p = 0ull, a1p = 0ull, a2p = 0ull, a3p = 0ull;
        CP_WAIT(3); __syncthreads(); DOT_RANGE(0, 16)
        CP_WAIT(2); __syncthreads(); DOT_RANGE(16, 32)
        CP_WAIT(1); __syncthreads(); DOT_RANGE(32, 48)
        CP_WAIT(0); __syncthreads(); DOT_RANGE(48, 64)

        float2 q0 = upk(a0p), q1 = upk(a1p), q2 = upk(a2p), q3 = upk(a3p);
        float a0 = ga0 + q0.x + q0.y;
        float a1 = ga1 + q1.x + q1.y;
        float a2 = ga2 + q2.x + q2.y;
        float a3 = ga3 + q3.x + q3.y;

        float si = sigf(a0);
        float sf = sigf(a1);
        float tg = tanhfast(a2);
        float so = sigf(a3);
        float cn = sf * c + si * tg;
        float hn = so * tanhfast(cn);
        h = mt * hn + (1.f - mt) * h;
        c = mt * cn + (1.f - mt) * c;

        sh_h[u * 64 + b] = h;
        __syncthreads();
        float4 v;
        if (tid < 64) {
            v = make_float4(sh_h[tid], sh_h[64 + tid], sh_h[128 + tid], sh_h[192 + tid]);
            __stcg(&((p ? hbuf0 : hbuf1)[kq * 64 + tid]), v);
        }
        __syncthreads();
        if (tid == 0) st_rel(myflag, base + s + 2);

        if (tid < 64)
            HoutD[((long)t * 64 + kq) * 64 + tid] = v;
    }
#undef DOT_RANGE
}

// =====================================================================
// K3: feats[t][b][j] = (sum_k (h[k]*m) * Wtag[j][k] + btag[j]) * m
// =====================================================================
__global__ void feats_kernel(const float* __restrict__ Wtag,
                             const float* __restrict__ btag,
                             const float* __restrict__ mask)
{
    __shared__ float Ws[TAGS_ * 512];
    __shared__ float bts[TAGS_];
    const int t   = blockIdx.x;
    const int tid = threadIdx.x;
    for (int i = tid; i < TAGS_ * 512; i += 256) Ws[i] = Wtag[i];
    if (tid < TAGS_) bts[tid] = btag[tid];
    __syncthreads();

    const int w    = tid >> 5;
    const int lane = tid & 31;
    const float* Hf = g_Hout + ((long)t * 256) * 64;
    const float* Hb = g_Hout + ((long)T_ * 256 + (long)t * 256) * 64;
    for (int b = w; b < B_; b += 8) {
        float mt = mask[t * B_ + b];
        float acc[TAGS_];
#pragma unroll
        for (int j = 0; j < TAGS_; j++) acc[j] = 0.f;
        for (int k = lane; k < HD_; k += 32) {
            float hv  = Hf[k * 64 + b] * mt;
            float hv2 = Hb[k * 64 + b] * mt;
#pragma unroll
            for (int j = 0; j < TAGS_; j++) {
                acc[j] = fmaf(hv,  Ws[j * 512 + k],       acc[j]);
                acc[j] = fmaf(hv2, Ws[j * 512 + HD_ + k], acc[j]);
            }
        }
#pragma unroll
        for (int j = 0; j < TAGS_; j++)
#pragma unroll
            for (int off = 16; off > 0; off >>= 1)
                acc[j] += __shfl_xor_sync(0xffffffffu, acc[j], off);
        if (lane < TAGS_)
            g_feats[(t * B_ + b) * TAGS_ + lane] = (acc[lane] + bts[lane]) * mt;
    }
}

// =====================================================================
// K4: Viterbi. 1 CTA/batch. Critical chain = fmax tree + shfl only;
// argmax via equality scan OFF the recurrence chain.
// =====================================================================
__global__ void viterbi_kernel(const float* __restrict__ trans,
                               const float* __restrict__ mask,
                               float* __restrict__ out, int out_size)
{
    __shared__ float fsh[T_ * TAGS_];
    __shared__ float msh[T_];
    __shared__ unsigned char ptrs[T_ * TAGS_];
    __shared__ float trs[TAGS_ * TAGS_];
    const int bb  = blockIdx.x;
    const int tid = threadIdx.x;   // 128

    for (int i = tid; i < T_ * TAGS_; i += 128) {
        int t = i / TAGS_, j = i % TAGS_;
        fsh[i] = g_feats[(t * B_ + bb) * TAGS_ + j];
    }
    for (int i = tid; i < T_; i += 128) msh[i] = mask[i * B_ + bb];
    for (int i = tid; i < TAGS_ * TAGS_; i += 128) trs[i] = trans[i];
    __syncthreads();
    if (tid >= 32) return;

    const int j  = tid;
    const int jc = (j < TAGS_) ? j : 0;
    float trow[TAGS_];
#pragma unroll
    for (int q = 0; q < TAGS_; q++) trow[q] = trs[jc * TAGS_ + q];

    float s[TAGS_];
#pragma unroll
    for (int q = 0; q < TAGS_; q++) s[q] = (q == 9) ? 0.f : NEGV;   // START=9

    for (int t = 0; t < T_; t++) {
        float ft = fsh[t * TAGS_ + jc];   // independent of chain
        float mt = msh[t];

        float v[TAGS_];
#pragma unroll
        for (int q = 0; q < TAGS_; q++) v[q] = s[q] + trow[q];

        // fmax tree, depth 4 (critical chain)
        float m0 = fmaxf(v[0], v[1]);
        float m1 = fmaxf(v[2], v[3]);
        float m2 = fmaxf(v[4], v[5]);
        float m3 = fmaxf(v[6], v[7]);
        float m4 = fmaxf(v[8], v[9]);
        float n0 = fmaxf(m0, m1);
        float n1 = fmaxf(m2, m3);
        float n2 = fmaxf(m4, v[10]);
        float best = fmaxf(fmaxf(n0, n1), n2);

        // argmax off-chain: lowest q with v[q] == best (matches jnp.argmax ties)
        int arg = 10;
#pragma unroll
        for (int q = 9; q >= 0; q--) arg = (v[q] == best) ? q : arg;
        if (j < TAGS_) ptrs[t * TAGS_ + j] = (unsigned char)arg;

        float ns = best + ft;
        float sn = (mt > 0.f) ? ns : s[jc];
#pragma unroll
        for (int q = 0; q < TAGS_; q++)
            s[q] = __shfl_sync(0xffffffffu, sn, q);
    }

    // final argmax locally (full vector in every lane)
    float fv[TAGS_];
#pragma unroll
    for (int q = 0; q < TAGS_; q++) fv[q] = s[q] + trs[10 * TAGS_ + q];   // STOP=10
    float fb = fv[0];
#pragma unroll
    for (int q = 1; q < TAGS_; q++) fb = fmaxf(fb, fv[q]);
    int fbt = 10;
#pragma unroll
    for (int q = 9; q >= 0; q--) fbt = (fv[q] == fb) ? q : fbt;

    if (tid == 0) {
        if (out_size >= B_ * T_ + B_) out[B_ * T_ + bb] = fb;
        int cur = fbt;
        for (int t = T_ - 1; t >= 0; t--) {
            if (bb * T_ + t < out_size) out[bb * T_ + t] = (float)cur;
            cur = ptrs[t * TAGS_ + cur];
        }
    }
}

// =====================================================================
extern "C" void kernel_launch(void* const* d_in, const int* in_sizes, int n_in,
                              void* d_out, int out_size)
{
    const int*   sent  = (const int*)d_in[0];
    const float* mask  = (const float*)d_in[1];
    const float* embed = (const float*)d_in[2];
    const float* Wih_f = (const float*)d_in[3];
    const float* Whh_f = (const float*)d_in[4];
    const float* b_f   = (const float*)d_in[5];
    const float* Wih_b = (const float*)d_in[6];
    const float* Whh_b = (const float*)d_in[7];
    const float* b_b   = (const float*)d_in[8];
    const float* h0f   = (const float*)d_in[9];
    const float* c0f   = (const float*)d_in[10];
    const float* h0b   = (const float*)d_in[11];
    const float* c0b   = (const float*)d_in[12];
    const float* Wtag  = (const float*)d_in[13];
    const float* btag  = (const float*)d_in[14];
    const float* trans = (const float*)d_in[15];

    gx_kernel<<<dim3(T_, 16), 256>>>(sent, embed, Wih_f, b_f, Wih_b, b_b);

    cudaFuncSetAttribute(lstm_kernel, cudaFuncAttributeMaxDynamicSharedMemorySize, LSTM_SMEM);
    lstm_kernel<<<LSTM_NB, 256, LSTM_SMEM>>>(Whh_f, Whh_b, h0f, c0f, h0b, c0b, mask);

    feats_kernel<<<T_, 256>>>(Wtag, btag, mask);

    viterbi_kernel<<<B_, 128>>>(trans, mask, (float*)d_out, out_size);
}

// round 11
// speedup vs baseline: 1.1134x; 1.1134x over previous
#include <cuda_runtime.h>
#include <math.h>

#define B_    64
#define T_    512
#define EMB_  256
#define HD_   256
#define G4_   1024
#define TAGS_ 11
#define NEGV  (-10000.0f)
#define GSTRIDE (256 * 64)   // gate stride in g_Gx elements

// ---------------- scratch (static device globals; no allocs) ----------------
__device__ __align__(16) float g_Gx[(long)2 * T_ * B_ * G4_];   // [dir][t][gate][unit][b]
__device__ __align__(16) float g_Hout[(long)2 * T_ * B_ * HD_]; // [dir][t][unit][b]
__device__ __align__(16) float g_hbuf[2 * 2 * B_ * HD_];        // [dir][buf][unitq][b] float4
__device__ __align__(16) float g_feats[T_ * B_ * TAGS_];
#define LSTM_NB 128
__device__ unsigned g_flags[LSTM_NB];   // monotonic epochs across graph replays

// ---------------- packed f32x2 helpers ----------------
__device__ __forceinline__ void ffma2(unsigned long long& d,
                                      unsigned long long a,
                                      unsigned long long b) {
    asm("fma.rn.f32x2 %0, %1, %2, %0;" : "+l"(d) : "l"(a), "l"(b));
}
__device__ __forceinline__ float2 upk(unsigned long long v) {
    float2 f; asm("mov.b64 {%0, %1}, %2;" : "=f"(f.x), "=f"(f.y) : "l"(v)); return f;
}

// ---------------- fast activations (MUFU-based, ~1e-6 rel err) ----------------
__device__ __forceinline__ float sigf(float x) {
    return __fdividef(1.f, 1.f + __expf(-x));
}
__device__ __forceinline__ float tanhfast(float x) {
    return fmaf(2.f, __fdividef(1.f, 1.f + __expf(-2.f * x)), -1.f);
}

// ---------------- release/acquire flag ops ----------------
__device__ __forceinline__ unsigned ld_acq(const unsigned* p) {
    unsigned v;
    asm volatile("ld.global.acquire.gpu.u32 %0, [%1];" : "=r"(v) : "l"(p));
    return v;
}
__device__ __forceinline__ void st_rel(unsigned* p, unsigned v) {
    asm volatile("st.global.release.gpu.u32 [%0], %1;" :: "l"(p), "r"(v) : "memory");
}

// =====================================================================
// K1: Gx = embed[sent] @ Wih.T + b, written as [dir][t][gate][unit][b].
// Epilogue staged through smem tile [128 cols][64 b] (stride 68),
// then fully-coalesced float4 stores.
// =====================================================================
#define GX_STAGE_FLOATS (128 * 68)

__global__ void gx_kernel(const int* __restrict__ sent,
                          const float* __restrict__ embed,
                          const float* __restrict__ Wf, const float* __restrict__ bf,
                          const float* __restrict__ Wb, const float* __restrict__ bb)
{
    __shared__ __align__(16) float Sm[GX_STAGE_FLOATS];
    float* As = Sm;                // [row][k] stride 36
    float* Bs = Sm + 64 * 36;      // [col][k] stride 36
    __shared__ int toks[64];

    const int t     = blockIdx.x;
    const int dir   = blockIdx.y >> 3;
    const int gcol0 = (blockIdx.y & 7) * 128;
    const float* __restrict__ W    = dir ? Wb : Wf;
    const float* __restrict__ bias = dir ? bb : bf;

    const int tid = threadIdx.x;
    if (tid < 64) toks[tid] = sent[tid * T_ + t];
    __syncthreads();

    const int rowg = tid & 7;
    const int colg = tid >> 3;

    unsigned long long acc[8][4];
#pragma unroll
    for (int i = 0; i < 8; i++)
#pragma unroll
        for (int j = 0; j < 4; j++) acc[i][j] = 0ull;

    for (int k0 = 0; k0 < EMB_; k0 += 32) {
#pragma unroll
        for (int i = 0; i < 2; i++) {
            int e = tid + i * 256, r = e >> 3, seg = e & 7;
            float4 va = *(const float4*)(embed + (long)toks[r] * EMB_ + k0 + seg * 4);
            *(float4*)&As[r * 36 + seg * 4] = va;
        }
#pragma unroll
        for (int i = 0; i < 4; i++) {
            int e = tid + i * 256, r = e >> 3, seg = e & 7;
            float4 vb = *(const float4*)(W + (long)(gcol0 + r) * EMB_ + k0 + seg * 4);
            *(float4*)&Bs[r * 36 + seg * 4] = vb;
        }
        __syncthreads();
#pragma unroll
        for (int k4 = 0; k4 < 8; k4++) {
            ulonglong2 bv[4];
#pragma unroll
            for (int j = 0; j < 4; j++)
                bv[j] = *(const ulonglong2*)&Bs[(colg * 4 + j) * 36 + k4 * 4];
#pragma unroll
            for (int i = 0; i < 8; i++) {
                ulonglong2 av = *(const ulonglong2*)&As[(rowg + 8 * i) * 36 + k4 * 4];
#pragma unroll
                for (int j = 0; j < 4; j++) {
                    ffma2(acc[i][j], av.x, bv[j].x);
                    ffma2(acc[i][j], av.y, bv[j].y);
                }
            }
        }
        __syncthreads();
    }
    __syncthreads();

    float* stage = Sm;
#pragma unroll
    for (int j = 0; j < 4; j++) {
        int colL = colg * 4 + j;
        float bsv = bias[gcol0 + colL];
#pragma unroll
        for (int i = 0; i < 8; i++) {
            float2 p = upk(acc[i][j]);
            stage[colL * 68 + rowg + 8 * i] = p.x + p.y + bsv;
        }
    }
    __syncthreads();

    const long tb = (long)dir * T_ + t;
#pragma unroll
    for (int i = 0; i < 8; i++) {
        int id   = tid + i * 256;
        int colL = id >> 4;
        int b4   = id & 15;
        int gcol = gcol0 + colL;
        long obase = ((tb * 4 + (gcol >> 8)) * 256 + (gcol & 255)) * 64;
        float4 v = *(float4*)&stage[colL * 68 + b4 * 4];
        *(float4*)(g_Gx + obase + b4 * 4) = v;
    }
}

// =====================================================================
// K2: persistent bidirectional LSTM, 128 CTAs x 256 threads (R8 structure).
// CTA = (dir, kq 4-unit group); thread b=tid&63, u=tid>>6.
// Half-split barrier: wait/stage/compute producers 0-31, then 32-63.
// CORRECT h indexing: hs2[kk*64+b] = h[4kk..4kk+3] of batch b (LDS.128).
// =====================================================================
#define WSTRIDE   260
#define SM_WSH    0
#define SM_HS4    (16 * WSTRIDE)
#define SM_SHH    (SM_HS4 + 64 * 64 * 4)
#define LSTM_SMEM ((SM_SHH + 256) * 4)

__global__ void __launch_bounds__(256, 1)
lstm_kernel(const float* __restrict__ Whh_f, const float* __restrict__ Whh_b,
            const float* __restrict__ h0f, const float* __restrict__ c0f,
            const float* __restrict__ h0b, const float* __restrict__ c0b,
            const float* __restrict__ mask)
{
    extern __shared__ __align__(16) float sm[];
    float*  Wsh  = sm + SM_WSH;
    float4* hs4  = (float4*)(sm + SM_HS4);
    float*  sh_h = sm + SM_SHH;

    const int cta = blockIdx.x;
    const int dir = cta >> 6;
    const int kq  = cta & 63;
    const int u0  = kq * 4;
    const int tid = threadIdx.x;
    const int b    = tid & 63;
    const int u    = tid >> 6;
    const int unit = u0 + u;

    const float* __restrict__ Whh = dir ? Whh_b : Whh_f;
    const float* __restrict__ h0  = dir ? h0b : h0f;
    const float* __restrict__ c0  = dir ? c0b : c0f;

    float4* hbuf0 = ((float4*)g_hbuf) + (dir * 2 + 0) * (64 * 64);
    float4* hbuf1 = ((float4*)g_hbuf) + (dir * 2 + 1) * (64 * 64);
    float4* HoutD = ((float4*)g_Hout) + (long)dir * T_ * 64 * 64;
    unsigned* myflag = &g_flags[cta];
    const unsigned* dflags = &g_flags[dir * 64];

    __shared__ unsigned sbase;
    if (tid == 0) sbase = ld_acq(myflag);
    __syncthreads();
    const unsigned base = sbase;

    // preload weight slice: Wsh[g*4+uu][k] = Whh[g*256 + u0+uu][k]
#pragma unroll
    for (int i = 0; i < 4; i++) {
        int f  = tid + i * 256;
        int r  = f >> 6;
        int k4 = f & 63;
        int grow = (r >> 2) * HD_ + u0 + (r & 3);
        float4 w = *(const float4*)(Whh + (long)grow * HD_ + k4 * 4);
        *(float4*)&Wsh[r * WSTRIDE + k4 * 4] = w;
    }

    float c = c0[b * HD_ + unit];
    float h = h0[b * HD_ + unit];

    sh_h[u * 64 + b] = h;
    __syncthreads();
    if (tid < 64) {
        float4 v = make_float4(sh_h[tid], sh_h[64 + tid], sh_h[128 + tid], sh_h[192 + tid]);
        __stcg(&hbuf0[kq * 64 + tid], v);
    }
    __syncthreads();
    if (tid == 0) st_rel(myflag, base + 1);

    const float* w0p = &Wsh[(0 + u) * WSTRIDE];
    const float* w1p = &Wsh[(4 + u) * WSTRIDE];
    const float* w2p = &Wsh[(8 + u) * WSTRIDE];
    const float* w3p = &Wsh[(12 + u) * WSTRIDE];
    const ulonglong2* hs2 = (const ulonglong2*)hs4;

#define DOT_RANGE(K0, K1)                                              \
    _Pragma("unroll 8")                                                \
    for (int kk = (K0); kk < (K1); kk++) {                             \
        ulonglong2 hv = hs2[kk * 64 + b];                              \
        ulonglong2 w0 = *(const ulonglong2*)&w0p[kk * 4];              \
        ulonglong2 w1 = *(const ulonglong2*)&w1p[kk * 4];              \
        ulonglong2 w2 = *(const ulonglong2*)&w2p[kk * 4];              \
        ulonglong2 w3 = *(const ulonglong2*)&w3p[kk * 4];              \
        ffma2(a0p, hv.x, w0.x); ffma2(a0p, hv.y, w0.y);                \
        ffma2(a1p, hv.x, w1.x); ffma2(a1p, hv.y, w1.y);                \
        ffma2(a2p, hv.x, w2.x); ffma2(a2p, hv.y, w2.y);                \
        ffma2(a3p, hv.x, w3.x); ffma2(a3p, hv.y, w3.y);                \
    }

    for (int s = 0; s < T_; s++) {
        const int t = dir ? (T_ - 1 - s) : s;
        const int p = s & 1;

        // prefetch gate pre-activations + mask (independent of barrier)
        const float* gx = g_Gx + (((long)dir * T_ + t) * 4 * 256 + unit) * 64 + b;
        float ga0 = __ldg(gx);
        float ga1 = __ldg(gx + GSTRIDE);
        float ga2 = __ldg(gx + 2 * GSTRIDE);
        float ga3 = __ldg(gx + 3 * GSTRIDE);
        float mt  = __ldg(mask + t * B_ + b);

        const float4* hin = p ? hbuf1 : hbuf0;
        unsigned long long a0p = 0ull, a1p = 0ull, a2p = 0ull, a3p = 0ull;

        // ---- first half: producers 0..31 (data e < 2048) ----
        if (tid < 32) {
            const unsigned* f = dflags + tid;
            while ((int)(ld_acq(f) - base) < (int)(s + 1)) { }
        }
        __syncthreads();
#pragma unroll
        for (int i = 0; i < 8; i++) {
            int e = tid + i * 256;
            hs4[e] = __ldcg(hin + e);
        }
        __syncthreads();
        DOT_RANGE(0, 32)

        // ---- second half: producers 32..63 ----
        if (tid >= 32 && tid < 64) {
            const unsigned* f = dflags + tid;
            while ((int)(ld_acq(f) - base) < (int)(s + 1)) { }
        }
        __syncthreads();
#pragma unroll
        for (int i = 8; i < 16; i++) {
            int e = tid + i * 256;
            hs4[e] = __ldcg(hin + e);
        }
        __syncthreads();
        DOT_RANGE(32, 64)

        float2 q0 = upk(a0p), q1 = upk(a1p), q2 = upk(a2p), q3 = upk(a3p);
        float a0 = ga0 + q0.x + q0.y;
        float a1 = ga1 + q1.x + q1.y;
        float a2 = ga2 + q2.x + q2.y;
        float a3 = ga3 + q3.x + q3.y;

        float si = sigf(a0);
        float sf = sigf(a1);
        float tg = tanhfast(a2);
        float so = sigf(a3);
        float cn = sf * c + si * tg;
        float hn = so * tanhfast(cn);
        h = mt * hn + (1.f - mt) * h;
        c = mt * cn + (1.f - mt) * c;

        sh_h[u * 64 + b] = h;
        __syncthreads();
        float4 v;
        if (tid < 64) {
            v = make_float4(sh_h[tid], sh_h[64 + tid], sh_h[128 + tid], sh_h[192 + tid]);
            __stcg(&((p ? hbuf0 : hbuf1)[kq * 64 + tid]), v);
        }
        __syncthreads();
        if (tid == 0) st_rel(myflag, base + s + 2);

        if (tid < 64)
            HoutD[((long)t * 64 + kq) * 64 + tid] = v;
    }
#undef DOT_RANGE
}

// =====================================================================
// K3: feats[t][b][j] = (sum_k (h[k]*m) * Wtag[j][k] + btag[j]) * m
// =====================================================================
__global__ void feats_kernel(const float* __restrict__ Wtag,
                             const float* __restrict__ btag,
                             const float* __restrict__ mask)
{
    __shared__ float Ws[TAGS_ * 512];
    __shared__ float bts[TAGS_];
    const int t   = blockIdx.x;
    const int tid = threadIdx.x;
    for (int i = tid; i < TAGS_ * 512; i += 256) Ws[i] = Wtag[i];
    if (tid < TAGS_) bts[tid] = btag[tid];
    __syncthreads();

    const int w    = tid >> 5;
    const int lane = tid & 31;
    const float* Hf = g_Hout + ((long)t * 256) * 64;
    const float* Hb = g_Hout + ((long)T_ * 256 + (long)t * 256) * 64;
    for (int b = w; b < B_; b += 8) {
        float mt = mask[t * B_ + b];
        float acc[TAGS_];
#pragma unroll
        for (int j = 0; j < TAGS_; j++) acc[j] = 0.f;
        for (int k = lane; k < HD_; k += 32) {
            float hv  = Hf[k * 64 + b] * mt;
            float hv2 = Hb[k * 64 + b] * mt;
#pragma unroll
            for (int j = 0; j < TAGS_; j++) {
                acc[j] = fmaf(hv,  Ws[j * 512 + k],       acc[j]);
                acc[j] = fmaf(hv2, Ws[j * 512 + HD_ + k], acc[j]);
            }
        }
#pragma unroll
        for (int j = 0; j < TAGS_; j++)
#pragma unroll
            for (int off = 16; off > 0; off >>= 1)
                acc[j] += __shfl_xor_sync(0xffffffffu, acc[j], off);
        if (lane < TAGS_)
            g_feats[(t * B_ + b) * TAGS_ + lane] = (acc[lane] + bts[lane]) * mt;
    }
}

// =====================================================================
// K4: Viterbi. 1 CTA/batch. Critical chain = fmax tree + shfl only;
// argmax via equality scan OFF the recurrence chain.
// =====================================================================
__global__ void viterbi_kernel(const float* __restrict__ trans,
                               const float* __restrict__ mask,
                               float* __restrict__ out, int out_size)
{
    __shared__ float fsh[T_ * TAGS_];
    __shared__ float msh[T_];
    __shared__ unsigned char ptrs[T_ * TAGS_];
    __shared__ float trs[TAGS_ * TAGS_];
    const int bb  = blockIdx.x;
    const int tid = threadIdx.x;   // 128

    for (int i = tid; i < T_ * TAGS_; i += 128) {
        int t = i / TAGS_, j = i % TAGS_;
        fsh[i] = g_feats[(t * B_ + bb) * TAGS_ + j];
    }
    for (int i = tid; i < T_; i += 128) msh[i] = mask[i * B_ + bb];
    for (int i = tid; i < TAGS_ * TAGS_; i += 128) trs[i] = trans[i];
    __syncthreads();
    if (tid >= 32) return;

    const int j  = tid;
    const int jc = (j < TAGS_) ? j : 0;
    float trow[TAGS_];
#pragma unroll
    for (int q = 0; q < TAGS_; q++) trow[q] = trs[jc * TAGS_ + q];

    float s[TAGS_];
#pragma unroll
    for (int q = 0; q < TAGS_; q++) s[q] = (q == 9) ? 0.f : NEGV;   // START=9

    for (int t = 0; t < T_; t++) {
        float ft = fsh[t * TAGS_ + jc];   // independent of chain
        float mt = msh[t];

        float v[TAGS_];
#pragma unroll
        for (int q = 0; q < TAGS_; q++) v[q] = s[q] + trow[q];

        // fmax tree, depth 4 (critical chain)
        float m0 = fmaxf(v[0], v[1]);
        float m1 = fmaxf(v[2], v[3]);
        float m2 = fmaxf(v[4], v[5]);
        float m3 = fmaxf(v[6], v[7]);
        float m4 = fmaxf(v[8], v[9]);
        float n0 = fmaxf(m0, m1);
        float n1 = fmaxf(m2, m3);
        float n2 = fmaxf(m4, v[10]);
        float best = fmaxf(fmaxf(n0, n1), n2);

        // argmax off-chain: lowest q with v[q] == best (matches jnp.argmax ties)
        int arg = 10;
#pragma unroll
        for (int q = 9; q >= 0; q--) arg = (v[q] == best) ? q : arg;
        if (j < TAGS_) ptrs[t * TAGS_ + j] = (unsigned char)arg;

        float ns = best + ft;
        float sn = (mt > 0.f) ? ns : s[jc];
#pragma unroll
        for (int q = 0; q < TAGS_; q++)
            s[q] = __shfl_sync(0xffffffffu, sn, q);
    }

    // final argmax locally (full vector in every lane)
    float fv[TAGS_];
#pragma unroll
    for (int q = 0; q < TAGS_; q++) fv[q] = s[q] + trs[10 * TAGS_ + q];   // STOP=10
    float fb = fv[0];
#pragma unroll
    for (int q = 1; q < TAGS_; q++) fb = fmaxf(fb, fv[q]);
    int fbt = 10;
#pragma unroll
    for (int q = 9; q >= 0; q--) fbt = (fv[q] == fb) ? q : fbt;

    if (tid == 0) {
        if (out_size >= B_ * T_ + B_) out[B_ * T_ + bb] = fb;
        int cur = fbt;
        for (int t = T_ - 1; t >= 0; t--) {
            if (bb * T_ + t < out_size) out[bb * T_ + t] = (float)cur;
            cur = ptrs[t * TAGS_ + cur];
        }
    }
}

// =====================================================================
extern "C" void kernel_launch(void* const* d_in, const int* in_sizes, int n_in,
                              void* d_out, int out_size)
{
    const int*   sent  = (const int*)d_in[0];
    const float* mask  = (const float*)d_in[1];
    const float* embed = (const float*)d_in[2];
    const float* Wih_f = (const float*)d_in[3];
    const float* Whh_f = (const float*)d_in[4];
    const float* b_f   = (const float*)d_in[5];
    const float* Wih_b = (const float*)d_in[6];
    const float* Whh_b = (const float*)d_in[7];
    const float* b_b   = (const float*)d_in[8];
    const float* h0f   = (const float*)d_in[9];
    const float* c0f   = (const float*)d_in[10];
    const float* h0b   = (const float*)d_in[11];
    const float* c0b   = (const float*)d_in[12];
    const float* Wtag  = (const float*)d_in[13];
    const float* btag  = (const float*)d_in[14];
    const float* trans = (const float*)d_in[15];

    gx_kernel<<<dim3(T_, 16), 256>>>(sent, embed, Wih_f, b_f, Wih_b, b_b);

    cudaFuncSetAttribute(lstm_kernel, cudaFuncAttributeMaxDynamicSharedMemorySize, LSTM_SMEM);
    lstm_kernel<<<LSTM_NB, 256, LSTM_SMEM>>>(Whh_f, Whh_b, h0f, c0f, h0b, c0b, mask);

    feats_kernel<<<T_, 256>>>(Wtag, btag, mask);

    viterbi_kernel<<<B_, 128>>>(trans, mask, (float*)d_out, out_size);
}

// round 13
// speedup vs baseline: 1.1667x; 1.0479x over previous
#include <cuda_runtime.h>
#include <math.h>

#define B_    64
#define T_    512
#define EMB_  256
#define HD_   256
#define G4_   1024
#define TAGS_ 11
#define NEGV  (-10000.0f)
#define GSTRIDE (256 * 64)   // gate stride in g_Gx elements

// ---------------- scratch (static device globals; no allocs) ----------------
__device__ __align__(16) float g_Gx[(long)2 * T_ * B_ * G4_];   // [dir][t][gate][unit][b]
__device__ __align__(16) float g_Hout[(long)2 * T_ * B_ * HD_]; // [dir][t][unit][b]
__device__ __align__(16) float g_hbuf[2 * 2 * B_ * HD_];        // [dir][buf][unitq][b] float4
__device__ __align__(16) float g_feats[T_ * B_ * TAGS_];
#define LSTM_NB 128
#define FPAD 32   // one flag per 128B cache line
__device__ __align__(128) unsigned g_flags[LSTM_NB * FPAD];     // monotonic epochs

// ---------------- packed f32x2 helpers ----------------
__device__ __forceinline__ void ffma2(unsigned long long& d,
                                      unsigned long long a,
                                      unsigned long long b) {
    asm("fma.rn.f32x2 %0, %1, %2, %0;" : "+l"(d) : "l"(a), "l"(b));
}
__device__ __forceinline__ float2 upk(unsigned long long v) {
    float2 f; asm("mov.b64 {%0, %1}, %2;" : "=f"(f.x), "=f"(f.y) : "l"(v)); return f;
}

// ---------------- fast activations (MUFU-based, ~1e-6 rel err) ----------------
__device__ __forceinline__ float sigf(float x) {
    return __fdividef(1.f, 1.f + __expf(-x));
}
__device__ __forceinline__ float tanhfast(float x) {
    return fmaf(2.f, __fdividef(1.f, 1.f + __expf(-2.f * x)), -1.f);
}

// ---------------- release/acquire flag ops ----------------
__device__ __forceinline__ unsigned ld_acq(const unsigned* p) {
    unsigned v;
    asm volatile("ld.global.acquire.gpu.u32 %0, [%1];" : "=r"(v) : "l"(p));
    return v;
}
__device__ __forceinline__ void st_rel(unsigned* p, unsigned v) {
    asm volatile("st.global.release.gpu.u32 [%0], %1;" :: "l"(p), "r"(v) : "memory");
}

// =====================================================================
// K1: Gx = embed[sent] @ Wih.T + b, written as [dir][t][gate][unit][b].
// =====================================================================
#define GX_STAGE_FLOATS (128 * 68)

__global__ void gx_kernel(const int* __restrict__ sent,
                          const float* __restrict__ embed,
                          const float* __restrict__ Wf, const float* __restrict__ bf,
                          const float* __restrict__ Wb, const float* __restrict__ bb)
{
    __shared__ __align__(16) float Sm[GX_STAGE_FLOATS];
    float* As = Sm;                // [row][k] stride 36
    float* Bs = Sm + 64 * 36;      // [col][k] stride 36
    __shared__ int toks[64];

    const int t     = blockIdx.x;
    const int dir   = blockIdx.y >> 3;
    const int gcol0 = (blockIdx.y & 7) * 128;
    const float* __restrict__ W    = dir ? Wb : Wf;
    const float* __restrict__ bias = dir ? bb : bf;

    const int tid = threadIdx.x;
    if (tid < 64) toks[tid] = sent[tid * T_ + t];
    __syncthreads();

    const int rowg = tid & 7;
    const int colg = tid >> 3;

    unsigned long long acc[8][4];
#pragma unroll
    for (int i = 0; i < 8; i++)
#pragma unroll
        for (int j = 0; j < 4; j++) acc[i][j] = 0ull;

    for (int k0 = 0; k0 < EMB_; k0 += 32) {
#pragma unroll
        for (int i = 0; i < 2; i++) {
            int e = tid + i * 256, r = e >> 3, seg = e & 7;
            float4 va = *(const float4*)(embed + (long)toks[r] * EMB_ + k0 + seg * 4);
            *(float4*)&As[r * 36 + seg * 4] = va;
        }
#pragma unroll
        for (int i = 0; i < 4; i++) {
            int e = tid + i * 256, r = e >> 3, seg = e & 7;
            float4 vb = *(const float4*)(W + (long)(gcol0 + r) * EMB_ + k0 + seg * 4);
            *(float4*)&Bs[r * 36 + seg * 4] = vb;
        }
        __syncthreads();
#pragma unroll
        for (int k4 = 0; k4 < 8; k4++) {
            ulonglong2 bv[4];
#pragma unroll
            for (int j = 0; j < 4; j++)
                bv[j] = *(const ulonglong2*)&Bs[(colg * 4 + j) * 36 + k4 * 4];
#pragma unroll
            for (int i = 0; i < 8; i++) {
                ulonglong2 av = *(const ulonglong2*)&As[(rowg + 8 * i) * 36 + k4 * 4];
#pragma unroll
                for (int j = 0; j < 4; j++) {
                    ffma2(acc[i][j], av.x, bv[j].x);
                    ffma2(acc[i][j], av.y, bv[j].y);
                }
            }
        }
        __syncthreads();
    }
    __syncthreads();

    float* stage = Sm;
#pragma unroll
    for (int j = 0; j < 4; j++) {
        int colL = colg * 4 + j;
        float bsv = bias[gcol0 + colL];
#pragma unroll
        for (int i = 0; i < 8; i++) {
            float2 p = upk(acc[i][j]);
            stage[colL * 68 + rowg + 8 * i] = p.x + p.y + bsv;
        }
    }
    __syncthreads();

    const long tb = (long)dir * T_ + t;
#pragma unroll
    for (int i = 0; i < 8; i++) {
        int id   = tid + i * 256;
        int colL = id >> 4;
        int b4   = id & 15;
        int gcol = gcol0 + colL;
        long obase = ((tb * 4 + (gcol >> 8)) * 256 + (gcol & 255)) * 64;
        float4 v = *(float4*)&stage[colL * 68 + b4 * 4];
        *(float4*)(g_Gx + obase + b4 * 4) = v;
    }
}

// =====================================================================
// K2: persistent bidirectional LSTM, 128 CTAs x 256 threads.
// CTA = (dir, kq 4-unit group); thread b=tid&63, u=tid>>6.
// Half-split barrier; line-padded flags (contention-free polling);
// direct scalar publish (no smem transpose on critical path).
// =====================================================================
#define WSTRIDE   260
#define SM_WSH    0
#define SM_HS4    (16 * WSTRIDE)
#define LSTM_SMEM ((SM_HS4 + 64 * 64 * 4) * 4)

__global__ void __launch_bounds__(256, 1)
lstm_kernel(const float* __restrict__ Whh_f, const float* __restrict__ Whh_b,
            const float* __restrict__ h0f, const float* __restrict__ c0f,
            const float* __restrict__ h0b, const float* __restrict__ c0b,
            const float* __restrict__ mask)
{
    extern __shared__ __align__(16) float sm[];
    float*  Wsh  = sm + SM_WSH;
    float4* hs4  = (float4*)(sm + SM_HS4);

    const int cta = blockIdx.x;
    const int dir = cta >> 6;
    const int kq  = cta & 63;
    const int u0  = kq * 4;
    const int tid = threadIdx.x;
    const int b    = tid & 63;
    const int u    = tid >> 6;
    const int unit = u0 + u;

    const float* __restrict__ Whh = dir ? Whh_b : Whh_f;
    const float* __restrict__ h0  = dir ? h0b : h0f;
    const float* __restrict__ c0  = dir ? c0b : c0f;

    float* hbuf0 = g_hbuf + (dir * 2 + 0) * (64 * 256);   // [kq][b] float4 as floats
    float* hbuf1 = g_hbuf + (dir * 2 + 1) * (64 * 256);
    float* HoutD = g_Hout + (long)dir * T_ * 64 * 256;
    unsigned* myflag = &g_flags[cta * FPAD];
    const unsigned* dflags = &g_flags[dir * 64 * FPAD];

    __shared__ unsigned sbase;
    if (tid == 0) sbase = ld_acq(myflag);
    __syncthreads();
    const unsigned base = sbase;

    // preload weight slice: Wsh[g*4+uu][k] = Whh[g*256 + u0+uu][k]
#pragma unroll
    for (int i = 0; i < 4; i++) {
        int f  = tid + i * 256;
        int r  = f >> 6;
        int k4 = f & 63;
        int grow = (r >> 2) * HD_ + u0 + (r & 3);
        float4 w = *(const float4*)(Whh + (long)grow * HD_ + k4 * 4);
        *(float4*)&Wsh[r * WSTRIDE + k4 * 4] = w;
    }

    float c = c0[b * HD_ + unit];
    float h = h0[b * HD_ + unit];

    // initial publish: scalar, element (kq*64 + b)*4 + u
    const int hoff = (kq * 64 + b) * 4 + u;
    __stcg(hbuf0 + hoff, h);
    __syncthreads();
    if (tid == 0) st_rel(myflag, base + 1);

    const float* w0p = &Wsh[(0 + u) * WSTRIDE];
    const float* w1p = &Wsh[(4 + u) * WSTRIDE];
    const float* w2p = &Wsh[(8 + u) * WSTRIDE];
    const float* w3p = &Wsh[(12 + u) * WSTRIDE];
    const ulonglong2* hs2 = (const ulonglong2*)hs4;

#define DOT_RANGE(K0, K1)                                              \
    _Pragma("unroll 8")                                                \
    for (int kk = (K0); kk < (K1); kk++) {                             \
        ulonglong2 hv = hs2[kk * 64 + b];                              \
        ulonglong2 w0 = *(const ulonglong2*)&w0p[kk * 4];              \
        ulonglong2 w1 = *(const ulonglong2*)&w1p[kk * 4];              \
        ulonglong2 w2 = *(const ulonglong2*)&w2p[kk * 4];              \
        ulonglong2 w3 = *(const ulonglong2*)&w3p[kk * 4];              \
        ffma2(a0p, hv.x, w0.x); ffma2(a0p, hv.y, w0.y);                \
        ffma2(a1p, hv.x, w1.x); ffma2(a1p, hv.y, w1.y);                \
        ffma2(a2p, hv.x, w2.x); ffma2(a2p, hv.y, w2.y);                \
        ffma2(a3p, hv.x, w3.x); ffma2(a3p, hv.y, w3.y);                \
    }

    for (int s = 0; s < T_; s++) {
        const int t = dir ? (T_ - 1 - s) : s;
        const int p = s & 1;

        // prefetch gate pre-activations + mask (independent of barrier)
        const float* gx = g_Gx + (((long)dir * T_ + t) * 4 * 256 + unit) * 64 + b;
        float ga0 = __ldg(gx);
        float ga1 = __ldg(gx + GSTRIDE);
        float ga2 = __ldg(gx + 2 * GSTRIDE);
        float ga3 = __ldg(gx + 3 * GSTRIDE);
        float mt  = __ldg(mask + t * B_ + b);

        const float4* hin = (const float4*)(p ? hbuf1 : hbuf0);
        unsigned long long a0p = 0ull, a1p = 0ull, a2p = 0ull, a3p = 0ull;

        // ---- first half: producers 0..31 (data e < 2048) ----
        if (tid < 32) {
            const unsigned* f = dflags + tid * FPAD;
            while ((int)(ld_acq(f) - base) < (int)(s + 1)) { }
        }
        __syncthreads();
#pragma unroll
        for (int i = 0; i < 8; i++) {
            int e = tid + i * 256;
            hs4[e] = __ldcg(hin + e);
        }
        __syncthreads();
        DOT_RANGE(0, 32)

        // ---- second half: producers 32..63 ----
        if (tid >= 32 && tid < 64) {
            const unsigned* f = dflags + tid * FPAD;
            while ((int)(ld_acq(f) - base) < (int)(s + 1)) { }
        }
        __syncthreads();
#pragma unroll
        for (int i = 8; i < 16; i++) {
            int e = tid + i * 256;
            hs4[e] = __ldcg(hin + e);
        }
        __syncthreads();
        DOT_RANGE(32, 64)

        float2 q0 = upk(a0p), q1 = upk(a1p), q2 = upk(a2p), q3 = upk(a3p);
        float a0 = ga0 + q0.x + q0.y;
        float a1 = ga1 + q1.x + q1.y;
        float a2 = ga2 + q2.x + q2.y;
        float a3 = ga3 + q3.x + q3.y;

        float si = sigf(a0);
        float sf = sigf(a1);
        float tg = tanhfast(a2);
        float so = sigf(a3);
        float cn = sf * c + si * tg;
        float hn = so * tanhfast(cn);
        h = mt * hn + (1.f - mt) * h;
        c = mt * cn + (1.f - mt) * c;

        // publish: direct scalar store, then flag (release after block sync)
        __stcg((p ? hbuf0 : hbuf1) + hoff, h);
        __syncthreads();
        if (tid == 0) st_rel(myflag, base + s + 2);

        // Hout store AFTER flag — off the critical path
        HoutD[((long)t * 64 + kq) * 256 + b * 4 + u] = h;
    }
#undef DOT_RANGE
}

// =====================================================================
// K3: feats[t][b][j] = (sum_k (h[k]*m) * Wtag[j][k] + btag[j]) * m
// =====================================================================
__global__ void feats_kernel(const float* __restrict__ Wtag,
                             const float* __restrict__ btag,
                             const float* __restrict__ mask)
{
    __shared__ float Ws[TAGS_ * 512];
    __shared__ float bts[TAGS_];
    const int t   = blockIdx.x;
    const int tid = threadIdx.x;
    for (int i = tid; i < TAGS_ * 512; i += 256) Ws[i] = Wtag[i];
    if (tid < TAGS_) bts[tid] = btag[tid];
    __syncthreads();

    const int w    = tid >> 5;
    const int lane = tid & 31;
    const float* Hf = g_Hout + ((long)t * 256) * 64;
    const float* Hb = g_Hout + ((long)T_ * 256 + (long)t * 256) * 64;
    for (int b = w; b < B_; b += 8) {
        float mt = mask[t * B_ + b];
        float acc[TAGS_];
#pragma unroll
        for (int j = 0; j < TAGS_; j++) acc[j] = 0.f;
        for (int k = lane; k < HD_; k += 32) {
            float hv  = Hf[k * 64 + b] * mt;
            float hv2 = Hb[k * 64 + b] * mt;
#pragma unroll
            for (int j = 0; j < TAGS_; j++) {
                acc[j] = fmaf(hv,  Ws[j * 512 + k],       acc[j]);
                acc[j] = fmaf(hv2, Ws[j * 512 + HD_ + k], acc[j]);
            }
        }
#pragma unroll
        for (int j = 0; j < TAGS_; j++)
#pragma unroll
            for (int off = 16; off > 0; off >>= 1)
                acc[j] += __shfl_xor_sync(0xffffffffu, acc[j], off);
        if (lane < TAGS_)
            g_feats[(t * B_ + b) * TAGS_ + lane] = (acc[lane] + bts[lane]) * mt;
    }
}

// =====================================================================
// K4: Viterbi. 1 CTA/batch. fmax-tree chain, off-chain argmax.
// =====================================================================
__global__ void viterbi_kernel(const float* __restrict__ trans,
                               const float* __restrict__ mask,
                               float* __restrict__ out, int out_size)
{
    __shared__ float fsh[T_ * TAGS_];
    __shared__ float msh[T_];
    __shared__ unsigned char ptrs[T_ * TAGS_];
    __shared__ float trs[TAGS_ * TAGS_];
    const int bb  = blockIdx.x;
    const int tid = threadIdx.x;   // 128

    for (int i = tid; i < T_ * TAGS_; i += 128) {
        int t = i / TAGS_, j = i % TAGS_;
        fsh[i] = g_feats[(t * B_ + bb) * TAGS_ + j];
    }
    for (int i = tid; i < T_; i += 128) msh[i] = mask[i * B_ + bb];
    for (int i = tid; i < TAGS_ * TAGS_; i += 128) trs[i] = trans[i];
    __syncthreads();
    if (tid >= 32) return;

    const int j  = tid;
    const int jc = (j < TAGS_) ? j : 0;
    float trow[TAGS_];
#pragma unroll
    for (int q = 0; q < TAGS_; q++) trow[q] = trs[jc * TAGS_ + q];

    float s[TAGS_];
#pragma unroll
    for (int q = 0; q < TAGS_; q++) s[q] = (q == 9) ? 0.f : NEGV;   // START=9

    for (int t = 0; t < T_; t++) {
        float ft = fsh[t * TAGS_ + jc];
        float mt = msh[t];

        float v[TAGS_];
#pragma unroll
        for (int q = 0; q < TAGS_; q++) v[q] = s[q] + trow[q];

        float m0 = fmaxf(v[0], v[1]);
        float m1 = fmaxf(v[2], v[3]);
        float m2 = fmaxf(v[4], v[5]);
        float m3 = fmaxf(v[6], v[7]);
        float m4 = fmaxf(v[8], v[9]);
        float n0 = fmaxf(m0, m1);
        float n1 = fmaxf(m2, m3);
        float n2 = fmaxf(m4, v[10]);
        float best = fmaxf(fmaxf(n0, n1), n2);

        int arg = 10;
#pragma unroll
        for (int q = 9; q >= 0; q--) arg = (v[q] == best) ? q : arg;
        if (j < TAGS_) ptrs[t * TAGS_ + j] = (unsigned char)arg;

        float ns = best + ft;
        float sn = (mt > 0.f) ? ns : s[jc];
#pragma unroll
        for (int q = 0; q < TAGS_; q++)
            s[q] = __shfl_sync(0xffffffffu, sn, q);
    }

    float fv[TAGS_];
#pragma unroll
    for (int q = 0; q < TAGS_; q++) fv[q] = s[q] + trs[10 * TAGS_ + q];   // STOP=10
    float fb = fv[0];
#pragma unroll
    for (int q = 1; q < TAGS_; q++) fb = fmaxf(fb, fv[q]);
    int fbt = 10;
#pragma unroll
    for (int q = 9; q >= 0; q--) fbt = (fv[q] == fb) ? q : fbt;

    if (tid == 0) {
        if (out_size >= B_ * T_ + B_) out[B_ * T_ + bb] = fb;
        int cur = fbt;
        for (int t = T_ - 1; t >= 0; t--) {
            if (bb * T_ + t < out_size) out[bb * T_ + t] = (float)cur;
            cur = ptrs[t * TAGS_ + cur];
        }
    }
}

// =====================================================================
extern "C" void kernel_launch(void* const* d_in, const int* in_sizes, int n_in,
                              void* d_out, int out_size)
{
    const int*   sent  = (const int*)d_in[0];
    const float* mask  = (const float*)d_in[1];
    const float* embed = (const float*)d_in[2];
    const float* Wih_f = (const float*)d_in[3];
    const float* Whh_f = (const float*)d_in[4];
    const float* b_f   = (const float*)d_in[5];
    const float* Wih_b = (const float*)d_in[6];
    const float* Whh_b = (const float*)d_in[7];
    const float* b_b   = (const float*)d_in[8];
    const float* h0f   = (const float*)d_in[9];
    const float* c0f   = (const float*)d_in[10];
    const float* h0b   = (const float*)d_in[11];
    const float* c0b   = (const float*)d_in[12];
    const float* Wtag  = (const float*)d_in[13];
    const float* btag  = (const float*)d_in[14];
    const float* trans = (const float*)d_in[15];

    gx_kernel<<<dim3(T_, 16), 256>>>(sent, embed, Wih_f, b_f, Wih_b, b_b);

    cudaFuncSetAttribute(lstm_kernel, cudaFuncAttributeMaxDynamicSharedMemorySize, LSTM_SMEM);
    lstm_kernel<<<LSTM_NB, 256, LSTM_SMEM>>>(Whh_f, Whh_b, h0f, c0f, h0b, c0b, mask);

    feats_kernel<<<T_, 256>>>(Wtag, btag, mask);

    viterbi_kernel<<<B_, 128>>>(trans, mask, (float*)d_out, out_size);
}

// round 14
// speedup vs baseline: 1.2267x; 1.0514x over previous
#include <cuda_runtime.h>
#include <math.h>

#define B_    64
#define T_    512
#define EMB_  256
#define HD_   256
#define G4_   1024
#define TAGS_ 11
#define NEGV  (-10000.0f)
#define GSTRIDE (256 * 64)   // gate stride in g_Gx elements

// ---------------- scratch (static device globals; no allocs) ----------------
__device__ __align__(16) float g_Gx[(long)2 * T_ * B_ * G4_];   // [dir][t][gate][unit][b]
__device__ __align__(16) float g_Hout[(long)2 * T_ * B_ * HD_]; // [dir][t][unit][b]
__device__ __align__(16) float g_hbuf[2 * 2 * B_ * HD_];        // [dir][buf][b][k]
__device__ __align__(16) float g_feats[T_ * B_ * TAGS_];
#define LSTM_NB 128
#define FPAD 32   // one flag per 128B cache line
__device__ __align__(128) unsigned g_flags[LSTM_NB * FPAD];     // monotonic epochs

// ---------------- packed f32x2 helpers ----------------
__device__ __forceinline__ void ffma2(unsigned long long& d,
                                      unsigned long long a,
                                      unsigned long long b) {
    asm("fma.rn.f32x2 %0, %1, %2, %0;" : "+l"(d) : "l"(a), "l"(b));
}
__device__ __forceinline__ float2 upk(unsigned long long v) {
    float2 f; asm("mov.b64 {%0, %1}, %2;" : "=f"(f.x), "=f"(f.y) : "l"(v)); return f;
}

// ---------------- fast activations (MUFU-based, ~1e-6 rel err) ----------------
__device__ __forceinline__ float sigf(float x) {
    return __fdividef(1.f, 1.f + __expf(-x));
}
__device__ __forceinline__ float tanhfast(float x) {
    return fmaf(2.f, __fdividef(1.f, 1.f + __expf(-2.f * x)), -1.f);
}

// ---------------- release/acquire flag ops ----------------
__device__ __forceinline__ unsigned ld_acq(const unsigned* p) {
    unsigned v;
    asm volatile("ld.global.acquire.gpu.u32 %0, [%1];" : "=r"(v) : "l"(p));
    return v;
}
__device__ __forceinline__ void st_rel(unsigned* p, unsigned v) {
    asm volatile("st.global.release.gpu.u32 [%0], %1;" :: "l"(p), "r"(v) : "memory");
}

// =====================================================================
// K1: Gx = embed[sent] @ Wih.T + b, written as [dir][t][gate][unit][b].
// (unchanged from R12)
// =====================================================================
#define GX_STAGE_FLOATS (128 * 68)

__global__ void gx_kernel(const int* __restrict__ sent,
                          const float* __restrict__ embed,
                          const float* __restrict__ Wf, const float* __restrict__ bf,
                          const float* __restrict__ Wb, const float* __restrict__ bb)
{
    __shared__ __align__(16) float Sm[GX_STAGE_FLOATS];
    float* As = Sm;                // [row][k] stride 36
    float* Bs = Sm + 64 * 36;      // [col][k] stride 36
    __shared__ int toks[64];

    const int t     = blockIdx.x;
    const int dir   = blockIdx.y >> 3;
    const int gcol0 = (blockIdx.y & 7) * 128;
    const float* __restrict__ W    = dir ? Wb : Wf;
    const float* __restrict__ bias = dir ? bb : bf;

    const int tid = threadIdx.x;
    if (tid < 64) toks[tid] = sent[tid * T_ + t];
    __syncthreads();

    const int rowg = tid & 7;
    const int colg = tid >> 3;

    unsigned long long acc[8][4];
#pragma unroll
    for (int i = 0; i < 8; i++)
#pragma unroll
        for (int j = 0; j < 4; j++) acc[i][j] = 0ull;

    for (int k0 = 0; k0 < EMB_; k0 += 32) {
#pragma unroll
        for (int i = 0; i < 2; i++) {
            int e = tid + i * 256, r = e >> 3, seg = e & 7;
            float4 va = *(const float4*)(embed + (long)toks[r] * EMB_ + k0 + seg * 4);
            *(float4*)&As[r * 36 + seg * 4] = va;
        }
#pragma unroll
        for (int i = 0; i < 4; i++) {
            int e = tid + i * 256, r = e >> 3, seg = e & 7;
            float4 vb = *(const float4*)(W + (long)(gcol0 + r) * EMB_ + k0 + seg * 4);
            *(float4*)&Bs[r * 36 + seg * 4] = vb;
        }
        __syncthreads();
#pragma unroll
        for (int k4 = 0; k4 < 8; k4++) {
            ulonglong2 bv[4];
#pragma unroll
            for (int j = 0; j < 4; j++)
                bv[j] = *(const ulonglong2*)&Bs[(colg * 4 + j) * 36 + k4 * 4];
#pragma unroll
            for (int i = 0; i < 8; i++) {
                ulonglong2 av = *(const ulonglong2*)&As[(rowg + 8 * i) * 36 + k4 * 4];
#pragma unroll
                for (int j = 0; j < 4; j++) {
                    ffma2(acc[i][j], av.x, bv[j].x);
                    ffma2(acc[i][j], av.y, bv[j].y);
                }
            }
        }
        __syncthreads();
    }
    __syncthreads();

    float* stage = Sm;
#pragma unroll
    for (int j = 0; j < 4; j++) {
        int colL = colg * 4 + j;
        float bsv = bias[gcol0 + colL];
#pragma unroll
        for (int i = 0; i < 8; i++) {
            float2 p = upk(acc[i][j]);
            stage[colL * 68 + rowg + 8 * i] = p.x + p.y + bsv;
        }
    }
    __syncthreads();

    const long tb = (long)dir * T_ + t;
#pragma unroll
    for (int i = 0; i < 8; i++) {
        int id   = tid + i * 256;
        int colL = id >> 4;
        int b4   = id & 15;
        int gcol = gcol0 + colL;
        long obase = ((tb * 4 + (gcol >> 8)) * 256 + (gcol & 255)) * 64;
        float4 v = *(float4*)&stage[colL * 68 + b4 * 4];
        *(float4*)(g_Gx + obase + b4 * 4) = v;
    }
}

// =====================================================================
// K2: persistent bidirectional LSTM, 128 CTAs x 256 threads.
// 2-D blocking: CTA = (dir, ug = 16-unit group, bg = 16-batch group).
// thread: b_loc = tid&15, u_loc = tid>>4.
// Per step: wait 16 flags (8+8 half-split), stage 16KB h, 4x256 dots,
// gates, publish. Gx prefetched ONE STEP AHEAD; mask in smem.
// smem: W 64x260 | h 16x260 | mask 512x16  = 115,968 B
// =====================================================================
#define WST       260
#define SM_W      0
#define SM_H      (64 * WST)                  // 16640
#define SM_MSK    (SM_H + 16 * WST)           // 20800
#define LSTM_SMEM ((SM_MSK + 512 * 16) * 4)   // 115968 B

__global__ void __launch_bounds__(256, 1)
lstm_kernel(const float* __restrict__ Whh_f, const float* __restrict__ Whh_b,
            const float* __restrict__ h0f, const float* __restrict__ c0f,
            const float* __restrict__ h0b, const float* __restrict__ c0b,
            const float* __restrict__ mask)
{
    extern __shared__ __align__(16) float sm[];
    float* Wsh = sm + SM_W;     // [g*16+u_loc][k] stride WST
    float* hsm = sm + SM_H;     // [b_loc][k]      stride WST
    float* msk = sm + SM_MSK;   // [t][b_loc]      stride 16

    const int cta  = blockIdx.x;
    const int dir  = cta >> 6;
    const int ug   = (cta & 63) >> 2;   // 0..15
    const int bg   = cta & 3;           // 0..3
    const int tid  = threadIdx.x;
    const int b_loc = tid & 15;
    const int u_loc = tid >> 4;
    const int unit = ug * 16 + u_loc;
    const int b    = bg * 16 + b_loc;

    const float* __restrict__ Whh = dir ? Whh_b : Whh_f;
    const float* __restrict__ h0  = dir ? h0b : h0f;
    const float* __restrict__ c0  = dir ? c0b : c0f;

    float* hbuf0 = g_hbuf + (dir * 2 + 0) * (64 * 256);   // [b][k]
    float* hbuf1 = g_hbuf + (dir * 2 + 1) * (64 * 256);
    float* HoutD = g_Hout + (long)dir * T_ * 64 * 256;    // [t][unit][b]
    unsigned* myflag = &g_flags[cta * FPAD];
    // producer CTA for (dir, ug', bg): index dir*64 + ug'*4 + bg
    const unsigned* pflag_base = &g_flags[(dir * 64 + bg) * FPAD];

    __shared__ unsigned sbase;
    if (tid == 0) sbase = ld_acq(myflag);
    __syncthreads();
    const unsigned base = sbase;

    // preload weight slice: Wsh[g*16+uu][k] = Whh[g*256 + ug*16+uu][k]
#pragma unroll
    for (int i = 0; i < 16; i++) {
        int f  = tid + i * 256;       // float4 idx 0..4095
        int r  = f >> 6;              // 0..63
        int k4 = f & 63;
        int grow = (r >> 4) * 256 + ug * 16 + (r & 15);
        float4 w = *(const float4*)(Whh + (long)grow * HD_ + k4 * 4);
        *(float4*)&Wsh[r * WST + k4 * 4] = w;
    }
    // preload mask slab: msk[t][b_loc] = mask[t*64 + bg*16 + b_loc]
#pragma unroll
    for (int i = 0; i < 32; i++) {
        int e = tid + i * 256;        // 0..8191
        int tt = e >> 4, bl = e & 15;
        msk[e] = mask[tt * B_ + bg * 16 + bl];
    }

    float c = c0[b * HD_ + unit];
    float h = h0[b * HD_ + unit];

    // initial publish
    __stcg(hbuf0 + b * 256 + unit, h);
    __syncthreads();
    if (tid == 0) st_rel(myflag, base + 1);

    const float* w0p = &Wsh[(0 * 16 + u_loc) * WST];
    const float* w1p = &Wsh[(1 * 16 + u_loc) * WST];
    const float* w2p = &Wsh[(2 * 16 + u_loc) * WST];
    const float* w3p = &Wsh[(3 * 16 + u_loc) * WST];
    const float* hrow = &hsm[b_loc * WST];

    // prefetch Gx + mask for step 0
    const int t0 = dir ? (T_ - 1) : 0;
    const float* gx0 = g_Gx + (((long)dir * T_ + t0) * 4 * 256 + unit) * 64 + b;
    float ga0 = __ldg(gx0);
    float ga1 = __ldg(gx0 + GSTRIDE);
    float ga2 = __ldg(gx0 + 2 * GSTRIDE);
    float ga3 = __ldg(gx0 + 3 * GSTRIDE);

#define DOT_RANGE(K0, K1)                                              \
    _Pragma("unroll 8")                                                \
    for (int kk = (K0); kk < (K1); kk++) {                             \
        ulonglong2 hv = *(const ulonglong2*)&hrow[kk * 4];             \
        ulonglong2 w0 = *(const ulonglong2*)&w0p[kk * 4];              \
        ulonglong2 w1 = *(const ulonglong2*)&w1p[kk * 4];              \
        ulonglong2 w2 = *(const ulonglong2*)&w2p[kk * 4];              \
        ulonglong2 w3 = *(const ulonglong2*)&w3p[kk * 4];              \
        ffma2(a0p, hv.x, w0.x); ffma2(a0p, hv.y, w0.y);                \
        ffma2(a1p, hv.x, w1.x); ffma2(a1p, hv.y, w1.y);                \
        ffma2(a2p, hv.x, w2.x); ffma2(a2p, hv.y, w2.y);                \
        ffma2(a3p, hv.x, w3.x); ffma2(a3p, hv.y, w3.y);                \
    }

    for (int s = 0; s < T_; s++) {
        const int t = dir ? (T_ - 1 - s) : s;
        const int p = s & 1;
        const float4* hin = (const float4*)((p ? hbuf1 : hbuf0) + bg * 16 * 256);

        unsigned long long a0p = 0ull, a1p = 0ull, a2p = 0ull, a3p = 0ull;

        // ---- first half: producers ug' 0..7 (units/k 0..127) ----
        if (tid < 8) {
            const unsigned* f = pflag_base + tid * 4 * FPAD;
            while ((int)(ld_acq(f) - base) < (int)(s + 1)) { }
        }
        __syncthreads();
#pragma unroll
        for (int i = 0; i < 2; i++) {
            int e = tid + i * 256;          // 0..511
            int row = e >> 5, c4 = e & 31;  // k 0..127
            *(float4*)&hsm[row * WST + c4 * 4] = __ldcg(hin + row * 64 + c4);
        }
        __syncthreads();
        DOT_RANGE(0, 32)

        // ---- second half: producers ug' 8..15 (units/k 128..255) ----
        if (tid >= 8 && tid < 16) {
            const unsigned* f = pflag_base + tid * 4 * FPAD;
            while ((int)(ld_acq(f) - base) < (int)(s + 1)) { }
        }
        __syncthreads();
#pragma unroll
        for (int i = 0; i < 2; i++) {
            int e = tid + i * 256;
            int row = e >> 5, c4 = 32 + (e & 31);
            *(float4*)&hsm[row * WST + c4 * 4] = __ldcg(hin + row * 64 + c4);
        }
        __syncthreads();
        DOT_RANGE(32, 64)

        float2 q0 = upk(a0p), q1 = upk(a1p), q2 = upk(a2p), q3 = upk(a3p);
        float a0 = ga0 + q0.x + q0.y;
        float a1 = ga1 + q1.x + q1.y;
        float a2 = ga2 + q2.x + q2.y;
        float a3 = ga3 + q3.x + q3.y;

        float mt = msk[t * 16 + b_loc];
        float si = sigf(a0);
        float sf = sigf(a1);
        float tg = tanhfast(a2);
        float so = sigf(a3);
        float cn = sf * c + si * tg;
        float hn = so * tanhfast(cn);
        h = mt * hn + (1.f - mt) * h;
        c = mt * cn + (1.f - mt) * c;

        // publish, then flag release
        __stcg((p ? hbuf0 : hbuf1) + b * 256 + unit, h);
        __syncthreads();
        if (tid == 0) st_rel(myflag, base + s + 2);

        // prefetch NEXT step's Gx (full step of DRAM-latency slack)
        if (s + 1 < T_) {
            const int tn = dir ? (T_ - 2 - s) : (s + 1);
            const float* gx = g_Gx + (((long)dir * T_ + tn) * 4 * 256 + unit) * 64 + b;
            ga0 = __ldg(gx);
            ga1 = __ldg(gx + GSTRIDE);
            ga2 = __ldg(gx + 2 * GSTRIDE);
            ga3 = __ldg(gx + 3 * GSTRIDE);
        }

        // Hout store AFTER flag — off the critical path
        HoutD[((long)t * 256 + unit) * 64 + b] = h;
    }
#undef DOT_RANGE
}

// =====================================================================
// K3: feats[t][b][j] = (sum_k (h[k]*m) * Wtag[j][k] + btag[j]) * m
// =====================================================================
__global__ void feats_kernel(const float* __restrict__ Wtag,
                             const float* __restrict__ btag,
                             const float* __restrict__ mask)
{
    __shared__ float Ws[TAGS_ * 512];
    __shared__ float bts[TAGS_];
    const int t   = blockIdx.x;
    const int tid = threadIdx.x;
    for (int i = tid; i < TAGS_ * 512; i += 256) Ws[i] = Wtag[i];
    if (tid < TAGS_) bts[tid] = btag[tid];
    __syncthreads();

    const int w    = tid >> 5;
    const int lane = tid & 31;
    const float* Hf = g_Hout + ((long)t * 256) * 64;
    const float* Hb = g_Hout + ((long)T_ * 256 + (long)t * 256) * 64;
    for (int b = w; b < B_; b += 8) {
        float mt = mask[t * B_ + b];
        float acc[TAGS_];
#pragma unroll
        for (int j = 0; j < TAGS_; j++) acc[j] = 0.f;
        for (int k = lane; k < HD_; k += 32) {
            float hv  = Hf[k * 64 + b] * mt;
            float hv2 = Hb[k * 64 + b] * mt;
#pragma unroll
            for (int j = 0; j < TAGS_; j++) {
                acc[j] = fmaf(hv,  Ws[j * 512 + k],       acc[j]);
                acc[j] = fmaf(hv2, Ws[j * 512 + HD_ + k], acc[j]);
            }
        }
#pragma unroll
        for (int j = 0; j < TAGS_; j++)
#pragma unroll
            for (int off = 16; off > 0; off >>= 1)
                acc[j] += __shfl_xor_sync(0xffffffffu, acc[j], off);
        if (lane < TAGS_)
            g_feats[(t * B_ + b) * TAGS_ + lane] = (acc[lane] + bts[lane]) * mt;
    }
}

// =====================================================================
// K4: Viterbi. 1 CTA/batch. fmax-tree chain, off-chain argmax.
// =====================================================================
__global__ void viterbi_kernel(const float* __restrict__ trans,
                               const float* __restrict__ mask,
                               float* __restrict__ out, int out_size)
{
    __shared__ float fsh[T_ * TAGS_];
    __shared__ float msh[T_];
    __shared__ unsigned char ptrs[T_ * TAGS_];
    __shared__ float trs[TAGS_ * TAGS_];
    const int bb  = blockIdx.x;
    const int tid = threadIdx.x;   // 128

    for (int i = tid; i < T_ * TAGS_; i += 128) {
        int t = i / TAGS_, j = i % TAGS_;
        fsh[i] = g_feats[(t * B_ + bb) * TAGS_ + j];
    }
    for (int i = tid; i < T_; i += 128) msh[i] = mask[i * B_ + bb];
    for (int i = tid; i < TAGS_ * TAGS_; i += 128) trs[i] = trans[i];
    __syncthreads();
    if (tid >= 32) return;

    const int j  = tid;
    const int jc = (j < TAGS_) ? j : 0;
    float trow[TAGS_];
#pragma unroll
    for (int q = 0; q < TAGS_; q++) trow[q] = trs[jc * TAGS_ + q];

    float s[TAGS_];
#pragma unroll
    for (int q = 0; q < TAGS_; q++) s[q] = (q == 9) ? 0.f : NEGV;   // START=9

    for (int t = 0; t < T_; t++) {
        float ft = fsh[t * TAGS_ + jc];
        float mt = msh[t];

        float v[TAGS_];
#pragma unroll
        for (int q = 0; q < TAGS_; q++) v[q] = s[q] + trow[q];

        float m0 = fmaxf(v[0], v[1]);
        float m1 = fmaxf(v[2], v[3]);
        float m2 = fmaxf(v[4], v[5]);
        float m3 = fmaxf(v[6], v[7]);
        float m4 = fmaxf(v[8], v[9]);
        float n0 = fmaxf(m0, m1);
        float n1 = fmaxf(m2, m3);
        float n2 = fmaxf(m4, v[10]);
        float best = fmaxf(fmaxf(n0, n1), n2);

        int arg = 10;
#pragma unroll
        for (int q = 9; q >= 0; q--) arg = (v[q] == best) ? q : arg;
        if (j < TAGS_) ptrs[t * TAGS_ + j] = (unsigned char)arg;

        float ns = best + ft;
        float sn = (mt > 0.f) ? ns : s[jc];
#pragma unroll
        for (int q = 0; q < TAGS_; q++)
            s[q] = __shfl_sync(0xffffffffu, sn, q);
    }

    float fv[TAGS_];
#pragma unroll
    for (int q = 0; q < TAGS_; q++) fv[q] = s[q] + trs[10 * TAGS_ + q];   // STOP=10
    float fb = fv[0];
#pragma unroll
    for (int q = 1; q < TAGS_; q++) fb = fmaxf(fb, fv[q]);
    int fbt = 10;
#pragma unroll
    for (int q = 9; q >= 0; q--) fbt = (fv[q] == fb) ? q : fbt;

    if (tid == 0) {
        if (out_size >= B_ * T_ + B_) out[B_ * T_ + bb] = fb;
        int cur = fbt;
        for (int t = T_ - 1; t >= 0; t--) {
            if (bb * T_ + t < out_size) out[bb * T_ + t] = (float)cur;
            cur = ptrs[t * TAGS_ + cur];
        }
    }
}

// =====================================================================
extern "C" void kernel_launch(void* const* d_in, const int* in_sizes, int n_in,
                              void* d_out, int out_size)
{
    const int*   sent  = (const int*)d_in[0];
    const float* mask  = (const float*)d_in[1];
    const float* embed = (const float*)d_in[2];
    const float* Wih_f = (const float*)d_in[3];
    const float* Whh_f = (const float*)d_in[4];
    const float* b_f   = (const float*)d_in[5];
    const float* Wih_b = (const float*)d_in[6];
    const float* Whh_b = (const float*)d_in[7];
    const float* b_b   = (const float*)d_in[8];
    const float* h0f   = (const float*)d_in[9];
    const float* c0f   = (const float*)d_in[10];
    const float* h0b   = (const float*)d_in[11];
    const float* c0b   = (const float*)d_in[12];
    const float* Wtag  = (const float*)d_in[13];
    const float* btag  = (const float*)d_in[14];
    const float* trans = (const float*)d_in[15];

    gx_kernel<<<dim3(T_, 16), 256>>>(sent, embed, Wih_f, b_f, Wih_b, b_b);

    cudaFuncSetAttribute(lstm_kernel, cudaFuncAttributeMaxDynamicSharedMemorySize, LSTM_SMEM);
    lstm_kernel<<<LSTM_NB, 256, LSTM_SMEM>>>(Whh_f, Whh_b, h0f, c0f, h0b, c0b, mask);

    feats_kernel<<<T_, 256>>>(Wtag, btag, mask);

    viterbi_kernel<<<B_, 128>>>(trans, mask, (float*)d_out, out_size);
}

// round 15
// speedup vs baseline: 1.2679x; 1.0336x over previous
#include <cuda_runtime.h>
#include <math.h>

#define B_    64
#define T_    512
#define EMB_  256
#define HD_   256
#define G4_   1024
#define TAGS_ 11
#define NEGV  (-10000.0f)
#define GSTRIDE (256 * 64)   // gate stride in g_Gx elements

// ---------------- scratch (static device globals; no allocs) ----------------
__device__ __align__(16) float g_Gx[(long)2 * T_ * B_ * G4_];   // [dir][t][gate][unit][b]
__device__ __align__(16) float g_Hout[(long)2 * T_ * B_ * HD_]; // [dir][t][unit][b]
__device__ __align__(16) float g_hbuf[2 * 2 * B_ * HD_];        // [dir][buf][b][k]
__device__ __align__(16) float g_feats[T_ * B_ * TAGS_];
#define LSTM_NB 256
#define FPAD 32   // one flag per 128B cache line
__device__ __align__(128) unsigned g_flags[LSTM_NB * FPAD];     // monotonic epochs

// ---------------- packed f32x2 helpers ----------------
__device__ __forceinline__ void ffma2(unsigned long long& d,
                                      unsigned long long a,
                                      unsigned long long b) {
    asm("fma.rn.f32x2 %0, %1, %2, %0;" : "+l"(d) : "l"(a), "l"(b));
}
__device__ __forceinline__ float2 upk(unsigned long long v) {
    float2 f; asm("mov.b64 {%0, %1}, %2;" : "=f"(f.x), "=f"(f.y) : "l"(v)); return f;
}

// ---------------- fast activations (MUFU-based, ~1e-6 rel err) ----------------
__device__ __forceinline__ float sigf(float x) {
    return __fdividef(1.f, 1.f + __expf(-x));
}
__device__ __forceinline__ float tanhfast(float x) {
    return fmaf(2.f, __fdividef(1.f, 1.f + __expf(-2.f * x)), -1.f);
}

// ---------------- release/acquire flag ops ----------------
__device__ __forceinline__ unsigned ld_acq(const unsigned* p) {
    unsigned v;
    asm volatile("ld.global.acquire.gpu.u32 %0, [%1];" : "=r"(v) : "l"(p));
    return v;
}
__device__ __forceinline__ void st_rel(unsigned* p, unsigned v) {
    asm volatile("st.global.release.gpu.u32 [%0], %1;" :: "l"(p), "r"(v) : "memory");
}

// =====================================================================
// K1: Gx = embed[sent] @ Wih.T + b, written as [dir][t][gate][unit][b].
// (unchanged)
// =====================================================================
#define GX_STAGE_FLOATS (128 * 68)

__global__ void gx_kernel(const int* __restrict__ sent,
                          const float* __restrict__ embed,
                          const float* __restrict__ Wf, const float* __restrict__ bf,
                          const float* __restrict__ Wb, const float* __restrict__ bb)
{
    __shared__ __align__(16) float Sm[GX_STAGE_FLOATS];
    float* As = Sm;                // [row][k] stride 36
    float* Bs = Sm + 64 * 36;      // [col][k] stride 36
    __shared__ int toks[64];

    const int t     = blockIdx.x;
    const int dir   = blockIdx.y >> 3;
    const int gcol0 = (blockIdx.y & 7) * 128;
    const float* __restrict__ W    = dir ? Wb : Wf;
    const float* __restrict__ bias = dir ? bb : bf;

    const int tid = threadIdx.x;
    if (tid < 64) toks[tid] = sent[tid * T_ + t];
    __syncthreads();

    const int rowg = tid & 7;
    const int colg = tid >> 3;

    unsigned long long acc[8][4];
#pragma unroll
    for (int i = 0; i < 8; i++)
#pragma unroll
        for (int j = 0; j < 4; j++) acc[i][j] = 0ull;

    for (int k0 = 0; k0 < EMB_; k0 += 32) {
#pragma unroll
        for (int i = 0; i < 2; i++) {
            int e = tid + i * 256, r = e >> 3, seg = e & 7;
            float4 va = *(const float4*)(embed + (long)toks[r] * EMB_ + k0 + seg * 4);
            *(float4*)&As[r * 36 + seg * 4] = va;
        }
#pragma unroll
        for (int i = 0; i < 4; i++) {
            int e = tid + i * 256, r = e >> 3, seg = e & 7;
            float4 vb = *(const float4*)(W + (long)(gcol0 + r) * EMB_ + k0 + seg * 4);
            *(float4*)&Bs[r * 36 + seg * 4] = vb;
        }
        __syncthreads();
#pragma unroll
        for (int k4 = 0; k4 < 8; k4++) {
            ulonglong2 bv[4];
#pragma unroll
            for (int j = 0; j < 4; j++)
                bv[j] = *(const ulonglong2*)&Bs[(colg * 4 + j) * 36 + k4 * 4];
#pragma unroll
            for (int i = 0; i < 8; i++) {
                ulonglong2 av = *(const ulonglong2*)&As[(rowg + 8 * i) * 36 + k4 * 4];
#pragma unroll
                for (int j = 0; j < 4; j++) {
                    ffma2(acc[i][j], av.x, bv[j].x);
                    ffma2(acc[i][j], av.y, bv[j].y);
                }
            }
        }
        __syncthreads();
    }
    __syncthreads();

    float* stage = Sm;
#pragma unroll
    for (int j = 0; j < 4; j++) {
        int colL = colg * 4 + j;
        float bsv = bias[gcol0 + colL];
#pragma unroll
        for (int i = 0; i < 8; i++) {
            float2 p = upk(acc[i][j]);
            stage[colL * 68 + rowg + 8 * i] = p.x + p.y + bsv;
        }
    }
    __syncthreads();

    const long tb = (long)dir * T_ + t;
#pragma unroll
    for (int i = 0; i < 8; i++) {
        int id   = tid + i * 256;
        int colL = id >> 4;
        int b4   = id & 15;
        int gcol = gcol0 + colL;
        long obase = ((tb * 4 + (gcol >> 8)) * 256 + (gcol & 255)) * 64;
        float4 v = *(float4*)&stage[colL * 68 + b4 * 4];
        *(float4*)(g_Gx + obase + b4 * 4) = v;
    }
}

// =====================================================================
// K2: persistent bidirectional LSTM, 256 CTAs x 128 threads, 2 CTAs/SM.
// CTA = (dir, ug = 8-unit group 0..31, bg = 16-batch group 0..3).
// thread: b_loc = tid&15, u_loc = tid>>4 (0..7).
// Per step: wait 32 producer flags (16+16 half-split), stage 16KB h,
// 4x256 dots, gates, publish. Gx+mask prefetched one step ahead.
// smem: W 32x260 + h 16x260 = 49,920 B  => occupancy 2/SM (latency overlap)
// =====================================================================
#define WST       260
#define SM_W      0
#define SM_H      (32 * WST)
#define LSTM_SMEM ((SM_H + 16 * WST) * 4)   // 49,920 B

__global__ void __launch_bounds__(128, 2)
lstm_kernel(const float* __restrict__ Whh_f, const float* __restrict__ Whh_b,
            const float* __restrict__ h0f, const float* __restrict__ c0f,
            const float* __restrict__ h0b, const float* __restrict__ c0b,
            const float* __restrict__ mask)
{
    extern __shared__ __align__(16) float sm[];
    float* Wsh = sm + SM_W;     // [g*8+u_loc][k] stride WST
    float* hsm = sm + SM_H;     // [b_loc][k]     stride WST

    const int cta  = blockIdx.x;
    const int dir  = cta >> 7;
    const int ug   = (cta & 127) >> 2;  // 0..31 (8 units each)
    const int bg   = cta & 3;           // 0..3  (16 batches each)
    const int tid  = threadIdx.x;
    const int b_loc = tid & 15;
    const int u_loc = tid >> 4;         // 0..7
    const int unit = ug * 8 + u_loc;
    const int b    = bg * 16 + b_loc;

    const float* __restrict__ Whh = dir ? Whh_b : Whh_f;
    const float* __restrict__ h0  = dir ? h0b : h0f;
    const float* __restrict__ c0  = dir ? c0b : c0f;

    float* hbuf0 = g_hbuf + (dir * 2 + 0) * (64 * 256);   // [b][k]
    float* hbuf1 = g_hbuf + (dir * 2 + 1) * (64 * 256);
    float* HoutD = g_Hout + (long)dir * T_ * 64 * 256;    // [t][unit][b]
    unsigned* myflag = &g_flags[cta * FPAD];
    // producer CTA for (dir, ug', bg): index dir*128 + ug'*4 + bg
    const unsigned* pflag_base = &g_flags[(dir * 128 + bg) * FPAD];

    __shared__ unsigned sbase;
    if (tid == 0) sbase = ld_acq(myflag);
    __syncthreads();
    const unsigned base = sbase;

    // preload weight slice: Wsh[g*8+uu][k] = Whh[g*256 + ug*8+uu][k]
#pragma unroll
    for (int i = 0; i < 16; i++) {
        int f  = tid + i * 128;       // float4 idx 0..2047
        int r  = f >> 6;              // 0..31
        int k4 = f & 63;
        int grow = (r >> 3) * 256 + ug * 8 + (r & 7);
        float4 w = *(const float4*)(Whh + (long)grow * HD_ + k4 * 4);
        *(float4*)&Wsh[r * WST + k4 * 4] = w;
    }

    float c = c0[b * HD_ + unit];
    float h = h0[b * HD_ + unit];

    // initial publish
    __stcg(hbuf0 + b * 256 + unit, h);
    __syncthreads();
    if (tid == 0) st_rel(myflag, base + 1);

    const float* w0p = &Wsh[(0 * 8 + u_loc) * WST];
    const float* w1p = &Wsh[(1 * 8 + u_loc) * WST];
    const float* w2p = &Wsh[(2 * 8 + u_loc) * WST];
    const float* w3p = &Wsh[(3 * 8 + u_loc) * WST];
    const float* hrow = &hsm[b_loc * WST];

    // prefetch Gx + mask for step 0
    const int t0 = dir ? (T_ - 1) : 0;
    const float* gx0 = g_Gx + (((long)dir * T_ + t0) * 4 * 256 + unit) * 64 + b;
    float ga0 = __ldg(gx0);
    float ga1 = __ldg(gx0 + GSTRIDE);
    float ga2 = __ldg(gx0 + 2 * GSTRIDE);
    float ga3 = __ldg(gx0 + 3 * GSTRIDE);
    float mt  = __ldg(mask + t0 * B_ + b);

#define DOT_RANGE(K0, K1)                                              \
    _Pragma("unroll 8")                                                \
    for (int kk = (K0); kk < (K1); kk++) {                             \
        ulonglong2 hv = *(const ulonglong2*)&hrow[kk * 4];             \
        ulonglong2 w0 = *(const ulonglong2*)&w0p[kk * 4];              \
        ulonglong2 w1 = *(const ulonglong2*)&w1p[kk * 4];              \
        ulonglong2 w2 = *(const ulonglong2*)&w2p[kk * 4];              \
        ulonglong2 w3 = *(const ulonglong2*)&w3p[kk * 4];              \
        ffma2(a0p, hv.x, w0.x); ffma2(a0p, hv.y, w0.y);                \
        ffma2(a1p, hv.x, w1.x); ffma2(a1p, hv.y, w1.y);                \
        ffma2(a2p, hv.x, w2.x); ffma2(a2p, hv.y, w2.y);                \
        ffma2(a3p, hv.x, w3.x); ffma2(a3p, hv.y, w3.y);                \
    }

    for (int s = 0; s < T_; s++) {
        const int t = dir ? (T_ - 1 - s) : s;
        const int p = s & 1;
        const float4* hin = (const float4*)((p ? hbuf1 : hbuf0) + bg * 16 * 256);

        unsigned long long a0p = 0ull, a1p = 0ull, a2p = 0ull, a3p = 0ull;

        // ---- first half: producers ug' 0..15 (k 0..127) ----
        if (tid < 16) {
            const unsigned* f = pflag_base + tid * 4 * FPAD;
            while ((int)(ld_acq(f) - base) < (int)(s + 1)) { }
        }
        __syncthreads();
#pragma unroll
        for (int i = 0; i < 4; i++) {
            int e = tid + i * 128;          // 0..511
            int row = e >> 5, c4 = e & 31;  // k 0..127
            *(float4*)&hsm[row * WST + c4 * 4] = __ldcg(hin + row * 64 + c4);
        }
        __syncthreads();
        DOT_RANGE(0, 32)

        // ---- second half: producers ug' 16..31 (k 128..255) ----
        if (tid >= 16 && tid < 32) {
            const unsigned* f = pflag_base + tid * 4 * FPAD;
            while ((int)(ld_acq(f) - base) < (int)(s + 1)) { }
        }
        __syncthreads();
#pragma unroll
        for (int i = 0; i < 4; i++) {
            int e = tid + i * 128;
            int row = e >> 5, c4 = 32 + (e & 31);
            *(float4*)&hsm[row * WST + c4 * 4] = __ldcg(hin + row * 64 + c4);
        }
        __syncthreads();
        DOT_RANGE(32, 64)

        float2 q0 = upk(a0p), q1 = upk(a1p), q2 = upk(a2p), q3 = upk(a3p);
        float a0 = ga0 + q0.x + q0.y;
        float a1 = ga1 + q1.x + q1.y;
        float a2 = ga2 + q2.x + q2.y;
        float a3 = ga3 + q3.x + q3.y;

        float si = sigf(a0);
        float sf = sigf(a1);
        float tg = tanhfast(a2);
        float so = sigf(a3);
        float cn = sf * c + si * tg;
        float hn = so * tanhfast(cn);
        h = mt * hn + (1.f - mt) * h;
        c = mt * cn + (1.f - mt) * c;

        // publish, then flag release
        __stcg((p ? hbuf0 : hbuf1) + b * 256 + unit, h);
        __syncthreads();
        if (tid == 0) st_rel(myflag, base + s + 2);

        // prefetch NEXT step's Gx + mask (full step of DRAM-latency slack)
        if (s + 1 < T_) {
            const int tn = dir ? (T_ - 2 - s) : (s + 1);
            const float* gx = g_Gx + (((long)dir * T_ + tn) * 4 * 256 + unit) * 64 + b;
            ga0 = __ldg(gx);
            ga1 = __ldg(gx + GSTRIDE);
            ga2 = __ldg(gx + 2 * GSTRIDE);
            ga3 = __ldg(gx + 3 * GSTRIDE);
            mt  = __ldg(mask + tn * B_ + b);
        }

        // Hout store AFTER flag — off the critical path
        HoutD[((long)t * 256 + unit) * 64 + b] = h;
    }
#undef DOT_RANGE
}

// =====================================================================
// K3: feats[t][b][j] = (sum_k (h[k]*m) * Wtag[j][k] + btag[j]) * m
// =====================================================================
__global__ void feats_kernel(const float* __restrict__ Wtag,
                             const float* __restrict__ btag,
                             const float* __restrict__ mask)
{
    __shared__ float Ws[TAGS_ * 512];
    __shared__ float bts[TAGS_];
    const int t   = blockIdx.x;
    const int tid = threadIdx.x;
    for (int i = tid; i < TAGS_ * 512; i += 256) Ws[i] = Wtag[i];
    if (tid < TAGS_) bts[tid] = btag[tid];
    __syncthreads();

    const int w    = tid >> 5;
    const int lane = tid & 31;
    const float* Hf = g_Hout + ((long)t * 256) * 64;
    const float* Hb = g_Hout + ((long)T_ * 256 + (long)t * 256) * 64;
    for (int b = w; b < B_; b += 8) {
        float mt = mask[t * B_ + b];
        float acc[TAGS_];
#pragma unroll
        for (int j = 0; j < TAGS_; j++) acc[j] = 0.f;
        for (int k = lane; k < HD_; k += 32) {
            float hv  = Hf[k * 64 + b] * mt;
            float hv2 = Hb[k * 64 + b] * mt;
#pragma unroll
            for (int j = 0; j < TAGS_; j++) {
                acc[j] = fmaf(hv,  Ws[j * 512 + k],       acc[j]);
                acc[j] = fmaf(hv2, Ws[j * 512 + HD_ + k], acc[j]);
            }
        }
#pragma unroll
        for (int j = 0; j < TAGS_; j++)
#pragma unroll
            for (int off = 16; off > 0; off >>= 1)
                acc[j] += __shfl_xor_sync(0xffffffffu, acc[j], off);
        if (lane < TAGS_)
            g_feats[(t * B_ + b) * TAGS_ + lane] = (acc[lane] + bts[lane]) * mt;
    }
}

// =====================================================================
// K4: Viterbi. 1 CTA/batch. fmax-tree chain, off-chain argmax.
// =====================================================================
__global__ void viterbi_kernel(const float* __restrict__ trans,
                               const float* __restrict__ mask,
                               float* __restrict__ out, int out_size)
{
    __shared__ float fsh[T_ * TAGS_];
    __shared__ float msh[T_];
    __shared__ unsigned char ptrs[T_ * TAGS_];
    __shared__ float trs[TAGS_ * TAGS_];
    const int bb  = blockIdx.x;
    const int tid = threadIdx.x;   // 128

    for (int i = tid; i < T_ * TAGS_; i += 128) {
        int t = i / TAGS_, j = i % TAGS_;
        fsh[i] = g_feats[(t * B_ + bb) * TAGS_ + j];
    }
    for (int i = tid; i < T_; i += 128) msh[i] = mask[i * B_ + bb];
    for (int i = tid; i < TAGS_ * TAGS_; i += 128) trs[i] = trans[i];
    __syncthreads();
    if (tid >= 32) return;

    const int j  = tid;
    const int jc = (j < TAGS_) ? j : 0;
    float trow[TAGS_];
#pragma unroll
    for (int q = 0; q < TAGS_; q++) trow[q] = trs[jc * TAGS_ + q];

    float s[TAGS_];
#pragma unroll
    for (int q = 0; q < TAGS_; q++) s[q] = (q == 9) ? 0.f : NEGV;   // START=9

    for (int t = 0; t < T_; t++) {
        float ft = fsh[t * TAGS_ + jc];
        float mt = msh[t];

        float v[TAGS_];
#pragma unroll
        for (int q = 0; q < TAGS_; q++) v[q] = s[q] + trow[q];

        float m0 = fmaxf(v[0], v[1]);
        float m1 = fmaxf(v[2], v[3]);
        float m2 = fmaxf(v[4], v[5]);
        float m3 = fmaxf(v[6], v[7]);
        float m4 = fmaxf(v[8], v[9]);
        float n0 = fmaxf(m0, m1);
        float n1 = fmaxf(m2, m3);
        float n2 = fmaxf(m4, v[10]);
        float best = fmaxf(fmaxf(n0, n1), n2);

        int arg = 10;
#pragma unroll
        for (int q = 9; q >= 0; q--) arg = (v[q] == best) ? q : arg;
        if (j < TAGS_) ptrs[t * TAGS_ + j] = (unsigned char)arg;

        float ns = best + ft;
        float sn = (mt > 0.f) ? ns : s[jc];
#pragma unroll
        for (int q = 0; q < TAGS_; q++)
            s[q] = __shfl_sync(0xffffffffu, sn, q);
    }

    float fv[TAGS_];
#pragma unroll
    for (int q = 0; q < TAGS_; q++) fv[q] = s[q] + trs[10 * TAGS_ + q];   // STOP=10
    float fb = fv[0];
#pragma unroll
    for (int q = 1; q < TAGS_; q++) fb = fmaxf(fb, fv[q]);
    int fbt = 10;
#pragma unroll
    for (int q = 9; q >= 0; q--) fbt = (fv[q] == fb) ? q : fbt;

    if (tid == 0) {
        if (out_size >= B_ * T_ + B_) out[B_ * T_ + bb] = fb;
        int cur = fbt;
        for (int t = T_ - 1; t >= 0; t--) {
            if (bb * T_ + t < out_size) out[bb * T_ + t] = (float)cur;
            cur = ptrs[t * TAGS_ + cur];
        }
    }
}

// =====================================================================
extern "C" void kernel_launch(void* const* d_in, const int* in_sizes, int n_in,
                              void* d_out, int out_size)
{
    const int*   sent  = (const int*)d_in[0];
    const float* mask  = (const float*)d_in[1];
    const float* embed = (const float*)d_in[2];
    const float* Wih_f = (const float*)d_in[3];
    const float* Whh_f = (const float*)d_in[4];
    const float* b_f   = (const float*)d_in[5];
    const float* Wih_b = (const float*)d_in[6];
    const float* Whh_b = (const float*)d_in[7];
    const float* b_b   = (const float*)d_in[8];
    const float* h0f   = (const float*)d_in[9];
    const float* c0f   = (const float*)d_in[10];
    const float* h0b   = (const float*)d_in[11];
    const float* c0b   = (const float*)d_in[12];
    const float* Wtag  = (const float*)d_in[13];
    const float* btag  = (const float*)d_in[14];
    const float* trans = (const float*)d_in[15];

    gx_kernel<<<dim3(T_, 16), 256>>>(sent, embed, Wih_f, b_f, Wih_b, b_b);

    cudaFuncSetAttribute(lstm_kernel, cudaFuncAttributeMaxDynamicSharedMemorySize, LSTM_SMEM);
    lstm_kernel<<<LSTM_NB, 128, LSTM_SMEM>>>(Whh_f, Whh_b, h0f, c0f, h0b, c0b, mask);

    feats_kernel<<<T_, 256>>>(Wtag, btag, mask);

    viterbi_kernel<<<B_, 128>>>(trans, mask, (float*)d_out, out_size);
}